// round 1
// baseline (speedup 1.0000x reference)
#include <cuda_runtime.h>

#define NC 16
#define DC 32
#define S_DIM 512
#define D_DIM 256
#define O_DIM 512   // NC*DC
#define B_DIM 256

// 256 MB scratch for u_hat [B, S, O] row-major (o = n*32 + d contiguous)
__device__ float g_uhat[(size_t)B_DIM * S_DIM * O_DIM];

// ---------------- GEMM: u_hat = x @ W ----------------
// A = x  [M=B*S, K=256] row-major
// B = W  [K=256, N=512] row-major
// C = u_hat [M, N] row-major
#define BM 128
#define BN 64
#define BK 16

__global__ __launch_bounds__(256) void caps_gemm(const float* __restrict__ A,
                                                 const float* __restrict__ Bmat) {
    __shared__ float As[BK][BM];
    __shared__ float Bs[BK][BN];
    const int K = D_DIM;
    const int N = O_DIM;
    const int tid = threadIdx.x;
    const int m0 = blockIdx.y * BM;
    const int n0 = blockIdx.x * BN;

    const int aRow = tid >> 2;         // 0..63
    const int aCol = (tid & 3) * 4;    // 0,4,8,12
    const int bRow = tid >> 4;         // 0..15
    const int bCol = (tid & 15) * 4;   // 0..60

    const int ty = tid >> 4;           // 0..15 -> 8 rows each
    const int tx = tid & 15;           // 0..15 -> 4 cols each

    float acc[8][4];
#pragma unroll
    for (int i = 0; i < 8; i++)
#pragma unroll
        for (int j = 0; j < 4; j++) acc[i][j] = 0.f;

    for (int k0 = 0; k0 < K; k0 += BK) {
#pragma unroll
        for (int r = 0; r < 2; r++) {
            const float4 a = *(const float4*)&A[(size_t)(m0 + aRow + r * 64) * K + k0 + aCol];
            As[aCol + 0][aRow + r * 64] = a.x;
            As[aCol + 1][aRow + r * 64] = a.y;
            As[aCol + 2][aRow + r * 64] = a.z;
            As[aCol + 3][aRow + r * 64] = a.w;
        }
        *(float4*)&Bs[bRow][bCol] =
            *(const float4*)&Bmat[(size_t)(k0 + bRow) * N + n0 + bCol];
        __syncthreads();
#pragma unroll
        for (int kk = 0; kk < BK; kk++) {
            const float4 b4 = *(const float4*)&Bs[kk][tx * 4];
            const float4 a0 = *(const float4*)&As[kk][ty * 8];
            const float4 a1 = *(const float4*)&As[kk][ty * 8 + 4];
            const float av[8] = {a0.x, a0.y, a0.z, a0.w, a1.x, a1.y, a1.z, a1.w};
            const float bv[4] = {b4.x, b4.y, b4.z, b4.w};
#pragma unroll
            for (int i = 0; i < 8; i++)
#pragma unroll
                for (int j = 0; j < 4; j++) acc[i][j] += av[i] * bv[j];
        }
        __syncthreads();
    }
#pragma unroll
    for (int i = 0; i < 8; i++) {
        float4 o;
        o.x = acc[i][0]; o.y = acc[i][1]; o.z = acc[i][2]; o.w = acc[i][3];
        *(float4*)&g_uhat[(size_t)(m0 + ty * 8 + i) * N + n0 + tx * 4] = o;
    }
}

// ---------------- Routing: 3 iterations, fused ----------------
// One CTA per batch b, 512 threads = 16 warps.
// iter 0: c uniform (1/16) -> outputs0 = squash(colsum/16)  (1 pass over u_hat)
// iter i (i=1,2): per s: b[n,s]=<out_{i-1}[n,:],u[n,s,:]>, softmax over n,
//                 accumulate out_i[n,d] += c[n,s]*u[n,s,d]  (1 pass each)
__global__ __launch_bounds__(512) void caps_routing(float* __restrict__ out) {
    __shared__ float s_out[O_DIM];
    __shared__ float s_acc[O_DIM];
    const int b = blockIdx.x;
    const int t = threadIdx.x;
    const int lane = t & 31;
    const int w = t >> 5;  // warp id 0..15
    const float* __restrict__ u = g_uhat + (size_t)b * S_DIM * O_DIM;

    // ---- iteration 0: uniform coupling ----
    float v = 0.f;
#pragma unroll 8
    for (int s = 0; s < S_DIM; s++) v += u[(size_t)s * O_DIM + t];
    v *= (1.f / 16.f);
    // squash: warp w == capsule n (32 lanes == 32 dims)
    float ss = v * v;
#pragma unroll
    for (int o = 16; o > 0; o >>= 1) ss += __shfl_xor_sync(0xffffffffu, ss, o);
    s_out[t] = v / sqrtf(ss + 1e-7f);
    __syncthreads();

    // ---- iterations 1 and 2 ----
    for (int it = 1; it < 3; it++) {
        s_acc[t] = 0.f;
        __syncthreads();

        float so[NC];
#pragma unroll
        for (int n = 0; n < NC; n++) so[n] = s_out[n * DC + lane];

        float lacc[NC];
#pragma unroll
        for (int n = 0; n < NC; n++) lacc[n] = 0.f;

        for (int s = w; s < S_DIM; s += 16) {
            const float* __restrict__ up = u + (size_t)s * O_DIM;
            float uv[NC];
#pragma unroll
            for (int n = 0; n < NC; n++) uv[n] = up[n * DC + lane];

            float bn[NC];
#pragma unroll
            for (int n = 0; n < NC; n++) {
                float p = so[n] * uv[n];
#pragma unroll
                for (int o = 16; o > 0; o >>= 1) p += __shfl_xor_sync(0xffffffffu, p, o);
                bn[n] = p;
            }
            // softmax over n (all lanes hold identical bn[])
            float mx = bn[0];
#pragma unroll
            for (int n = 1; n < NC; n++) mx = fmaxf(mx, bn[n]);
            float den = 0.f;
#pragma unroll
            for (int n = 0; n < NC; n++) { bn[n] = __expf(bn[n] - mx); den += bn[n]; }
            const float inv = 1.f / den;
#pragma unroll
            for (int n = 0; n < NC; n++) lacc[n] += bn[n] * inv * uv[n];
        }
#pragma unroll
        for (int n = 0; n < NC; n++) atomicAdd(&s_acc[n * DC + lane], lacc[n]);
        __syncthreads();

        const float vv = s_acc[t];
        float ss2 = vv * vv;
#pragma unroll
        for (int o = 16; o > 0; o >>= 1) ss2 += __shfl_xor_sync(0xffffffffu, ss2, o);
        const float res = vv / sqrtf(ss2 + 1e-7f);
        if (it == 2) {
            out[(size_t)b * O_DIM + t] = res;
        } else {
            s_out[t] = res;
        }
        __syncthreads();
    }
}

extern "C" void kernel_launch(void* const* d_in, const int* in_sizes, int n_in,
                              void* d_out, int out_size) {
    const float* x = (const float*)d_in[0];
    const float* W = (const float*)d_in[1];
    float* out = (float*)d_out;

    dim3 ggrid(O_DIM / BN, (B_DIM * S_DIM) / BM);  // (8, 1024)
    caps_gemm<<<ggrid, 256>>>(x, W);
    caps_routing<<<B_DIM, 512>>>(out);
}

// round 3
// speedup vs baseline: 1.4631x; 1.4631x over previous
#include <cuda_runtime.h>
#include <cuda_bf16.h>
#include <cstdint>

#define NC 16
#define DC 32
#define S_DIM 512
#define D_DIM 256
#define O_DIM 512   // NC*DC
#define B_DIM 256

// 256 MB scratch for u_hat [B*S, O] row-major
__device__ float g_uhat[(size_t)B_DIM * S_DIM * O_DIM];

// ---------------- mma.sync helpers (sm_80+ baseline, valid on compute_103) ----------------
#define LDMX4(r, addr)                                                                   \
    asm volatile("ldmatrix.sync.aligned.m8n8.x4.shared.b16 {%0,%1,%2,%3}, [%4];"         \
                 : "=r"((r)[0]), "=r"((r)[1]), "=r"((r)[2]), "=r"((r)[3]) : "r"(addr))
#define LDMX4T(r, addr)                                                                  \
    asm volatile("ldmatrix.sync.aligned.m8n8.x4.trans.shared.b16 {%0,%1,%2,%3}, [%4];"   \
                 : "=r"((r)[0]), "=r"((r)[1]), "=r"((r)[2]), "=r"((r)[3]) : "r"(addr))
#define MMA_BF16(d, a, b0, b1)                                                           \
    asm volatile("mma.sync.aligned.m16n8k16.row.col.f32.bf16.bf16.f32 "                  \
                 "{%0,%1,%2,%3}, {%4,%5,%6,%7}, {%8,%9}, {%0,%1,%2,%3};"                 \
                 : "+f"((d)[0]), "+f"((d)[1]), "+f"((d)[2]), "+f"((d)[3])                \
                 : "r"((a)[0]), "r"((a)[1]), "r"((a)[2]), "r"((a)[3]), "r"(b0), "r"(b1))

__device__ __forceinline__ uint32_t smem_u32(const void* p) {
    uint32_t a;
    asm("{ .reg .u64 t; cvta.to.shared.u64 t, %1; cvt.u32.u64 %0, t; }" : "=r"(a) : "l"(p));
    return a;
}

__device__ __forceinline__ uint32_t pack_split(float a, float b, uint32_t& lo) {
    __nv_bfloat16 ha = __float2bfloat16(a);
    __nv_bfloat16 hb = __float2bfloat16(b);
    __nv_bfloat16 la = __float2bfloat16(a - __bfloat162float(ha));
    __nv_bfloat16 lb = __float2bfloat16(b - __bfloat162float(hb));
    __nv_bfloat162 H(ha, hb), L(la, lb);
    lo = *(uint32_t*)&L;
    return *(uint32_t*)&H;
}

// ---------------- GEMM: u_hat[M=131072, 512] = x[M, 256] @ W[256, 512] ----------------
// CTA tile 128x128, BK=32, 512 threads = 16 warps (4x4), warp tile 32x32.
// A stored [m][k] (pad stride 40 bf16 = 80 B), B stored [k][n] (pad 136 bf16 = 272 B),
// both in hi/lo bf16 split; B loaded with ldmatrix.trans.
#define A_STR 40
#define B_STR 136

__global__ __launch_bounds__(512) void caps_gemm(const float* __restrict__ A,
                                                 const float* __restrict__ W) {
    __shared__ __align__(16) __nv_bfloat16 sAh[128 * A_STR];
    __shared__ __align__(16) __nv_bfloat16 sAl[128 * A_STR];
    __shared__ __align__(16) __nv_bfloat16 sBh[32 * B_STR];
    __shared__ __align__(16) __nv_bfloat16 sBl[32 * B_STR];

    const int tid = threadIdx.x;
    const int wid = tid >> 5;
    const int lane = tid & 31;
    const int wm = wid >> 2;   // 0..3
    const int wn = wid & 3;    // 0..3
    const int m0 = blockIdx.y * 128;
    const int n0 = blockIdx.x * 128;

    // per-lane ldmatrix byte offsets
    const int mat = lane >> 3, r = lane & 7;
    uint32_t a_off[2], b_off[2];
#pragma unroll
    for (int fm = 0; fm < 2; fm++)
        a_off[fm] = (uint32_t)(((wm * 32 + fm * 16 + (mat & 1) * 8 + r) * A_STR +
                                (mat >> 1) * 8) * 2);
#pragma unroll
    for (int nf2 = 0; nf2 < 2; nf2++)
        b_off[nf2] = (uint32_t)((((mat & 1) * 8 + r) * B_STR +
                                 (mat >> 1) * 8 + wn * 32 + nf2 * 16) * 2);

    const uint32_t sAh_b = smem_u32(sAh), sAl_b = smem_u32(sAl);
    const uint32_t sBh_b = smem_u32(sBh), sBl_b = smem_u32(sBl);

    float acc[2][4][4];
#pragma unroll
    for (int i = 0; i < 2; i++)
#pragma unroll
        for (int j = 0; j < 4; j++)
#pragma unroll
            for (int k = 0; k < 4; k++) acc[i][j][k] = 0.f;

    // global load assignments
    const int arow = tid >> 2, aq = tid & 3;      // A: 128 rows x 4 quads of 8
    const int bk = tid >> 4, bng = tid & 15;      // B: 32 k-rows x 16 groups of 8
    const float* gA = &A[(size_t)(m0 + arow) * D_DIM + aq * 8];
    const float* gW = &W[(size_t)bk * O_DIM + n0 + bng * 8];

    for (int kc = 0; kc < D_DIM / 32; kc++) {
        const float4 av0 = *(const float4*)(gA + kc * 32);
        const float4 av1 = *(const float4*)(gA + kc * 32 + 4);
        const float4 bv0 = *(const float4*)(gW + (size_t)kc * 32 * O_DIM);
        const float4 bv1 = *(const float4*)(gW + (size_t)kc * 32 * O_DIM + 4);
        __syncthreads();  // previous iter's ldmatrix done
        {
            uint4 hi, lo;
            hi.x = pack_split(av0.x, av0.y, lo.x);
            hi.y = pack_split(av0.z, av0.w, lo.y);
            hi.z = pack_split(av1.x, av1.y, lo.z);
            hi.w = pack_split(av1.z, av1.w, lo.w);
            *(uint4*)&sAh[arow * A_STR + aq * 8] = hi;
            *(uint4*)&sAl[arow * A_STR + aq * 8] = lo;
            hi.x = pack_split(bv0.x, bv0.y, lo.x);
            hi.y = pack_split(bv0.z, bv0.w, lo.y);
            hi.z = pack_split(bv1.x, bv1.y, lo.z);
            hi.w = pack_split(bv1.z, bv1.w, lo.w);
            *(uint4*)&sBh[bk * B_STR + bng * 8] = hi;
            *(uint4*)&sBl[bk * B_STR + bng * 8] = lo;
        }
        __syncthreads();

#pragma unroll
        for (int ks = 0; ks < 2; ks++) {
            uint32_t Ah[2][4], Al[2][4];
#pragma unroll
            for (int fm = 0; fm < 2; fm++) {
                LDMX4(Ah[fm], sAh_b + a_off[fm] + ks * 32);
                LDMX4(Al[fm], sAl_b + a_off[fm] + ks * 32);
            }
#pragma unroll
            for (int nf2 = 0; nf2 < 2; nf2++) {
                uint32_t Bh[4], Bl[4];
                LDMX4T(Bh, sBh_b + b_off[nf2] + ks * 16 * B_STR * 2);
                LDMX4T(Bl, sBl_b + b_off[nf2] + ks * 16 * B_STR * 2);
#pragma unroll
                for (int fm = 0; fm < 2; fm++) {
                    const int fn = nf2 * 2;
                    MMA_BF16(acc[fm][fn], Ah[fm], Bh[0], Bh[1]);      // hi*hi
                    MMA_BF16(acc[fm][fn], Ah[fm], Bl[0], Bl[1]);      // hi*lo
                    MMA_BF16(acc[fm][fn], Al[fm], Bh[0], Bh[1]);      // lo*hi
                    MMA_BF16(acc[fm][fn + 1], Ah[fm], Bh[2], Bh[3]);
                    MMA_BF16(acc[fm][fn + 1], Ah[fm], Bl[2], Bl[3]);
                    MMA_BF16(acc[fm][fn + 1], Al[fm], Bh[2], Bh[3]);
                }
            }
        }
    }

    // epilogue: acc -> g_uhat
#pragma unroll
    for (int fm = 0; fm < 2; fm++) {
        const int gm = m0 + wm * 32 + fm * 16 + (lane >> 2);
#pragma unroll
        for (int fn = 0; fn < 4; fn++) {
            const int gc = n0 + wn * 32 + fn * 8 + (lane & 3) * 2;
            float* p = &g_uhat[(size_t)gm * O_DIM + gc];
            *(float2*)p = make_float2(acc[fm][fn][0], acc[fm][fn][1]);
            *(float2*)(p + (size_t)8 * O_DIM) = make_float2(acc[fm][fn][2], acc[fm][fn][3]);
        }
    }
}

// ---------------- Routing (unchanged from R1) ----------------
__global__ __launch_bounds__(512) void caps_routing(float* __restrict__ out) {
    __shared__ float s_out[O_DIM];
    __shared__ float s_acc[O_DIM];
    const int b = blockIdx.x;
    const int t = threadIdx.x;
    const int lane = t & 31;
    const int w = t >> 5;
    const float* __restrict__ u = g_uhat + (size_t)b * S_DIM * O_DIM;

    float v = 0.f;
#pragma unroll 8
    for (int s = 0; s < S_DIM; s++) v += u[(size_t)s * O_DIM + t];
    v *= (1.f / 16.f);
    float ss = v * v;
#pragma unroll
    for (int o = 16; o > 0; o >>= 1) ss += __shfl_xor_sync(0xffffffffu, ss, o);
    s_out[t] = v / sqrtf(ss + 1e-7f);
    __syncthreads();

    for (int it = 1; it < 3; it++) {
        s_acc[t] = 0.f;
        __syncthreads();

        float so[NC];
#pragma unroll
        for (int n = 0; n < NC; n++) so[n] = s_out[n * DC + lane];
        float lacc[NC];
#pragma unroll
        for (int n = 0; n < NC; n++) lacc[n] = 0.f;

        for (int s = w; s < S_DIM; s += 16) {
            const float* __restrict__ up = u + (size_t)s * O_DIM;
            float uv[NC];
#pragma unroll
            for (int n = 0; n < NC; n++) uv[n] = up[n * DC + lane];

            float bn[NC];
#pragma unroll
            for (int n = 0; n < NC; n++) {
                float p = so[n] * uv[n];
#pragma unroll
                for (int o = 16; o > 0; o >>= 1) p += __shfl_xor_sync(0xffffffffu, p, o);
                bn[n] = p;
            }
            float mx = bn[0];
#pragma unroll
            for (int n = 1; n < NC; n++) mx = fmaxf(mx, bn[n]);
            float den = 0.f;
#pragma unroll
            for (int n = 0; n < NC; n++) { bn[n] = __expf(bn[n] - mx); den += bn[n]; }
            const float inv = 1.f / den;
#pragma unroll
            for (int n = 0; n < NC; n++) lacc[n] += bn[n] * inv * uv[n];
        }
#pragma unroll
        for (int n = 0; n < NC; n++) atomicAdd(&s_acc[n * DC + lane], lacc[n]);
        __syncthreads();

        const float vv = s_acc[t];
        float ss2 = vv * vv;
#pragma unroll
        for (int o = 16; o > 0; o >>= 1) ss2 += __shfl_xor_sync(0xffffffffu, ss2, o);
        const float res = vv / sqrtf(ss2 + 1e-7f);
        if (it == 2) out[(size_t)b * O_DIM + t] = res;
        else s_out[t] = res;
        __syncthreads();
    }
}

extern "C" void kernel_launch(void* const* d_in, const int* in_sizes, int n_in,
                              void* d_out, int out_size) {
    const float* x = (const float*)d_in[0];
    const float* W = (const float*)d_in[1];
    float* out = (float*)d_out;

    dim3 grid(O_DIM / 128, (B_DIM * S_DIM) / 128);  // (4, 1024)
    caps_gemm<<<grid, 512>>>(x, W);
    caps_routing<<<B_DIM, 512>>>(out);
}

// round 4
// speedup vs baseline: 1.6683x; 1.1403x over previous
#include <cuda_runtime.h>
#include <cuda_bf16.h>
#include <cstdint>

#define NC 16
#define DC 32
#define S_DIM 512
#define D_DIM 256
#define O_DIM 512
#define B_DIM 256
#define M_DIM (B_DIM * S_DIM)  // 131072

// u_hat TRANSPOSED: [b][o][s]  (o = n*32+d)
__device__ float g_uhat[(size_t)B_DIM * O_DIM * S_DIM];
// bf16 splits: xs[m][0..255]=hi, [256..511]=lo ; ws[k][n] hi rows 0..255, lo rows 256..511
__device__ __nv_bfloat16 g_xs[(size_t)M_DIM * 512];
__device__ __nv_bfloat16 g_ws[512 * 512];

// ---------------- PTX helpers ----------------
#define LDMX4(r, addr)                                                                   \
    asm volatile("ldmatrix.sync.aligned.m8n8.x4.shared.b16 {%0,%1,%2,%3}, [%4];"         \
                 : "=r"((r)[0]), "=r"((r)[1]), "=r"((r)[2]), "=r"((r)[3]) : "r"(addr))
#define LDMX4T(r, addr)                                                                  \
    asm volatile("ldmatrix.sync.aligned.m8n8.x4.trans.shared.b16 {%0,%1,%2,%3}, [%4];"   \
                 : "=r"((r)[0]), "=r"((r)[1]), "=r"((r)[2]), "=r"((r)[3]) : "r"(addr))
#define MMA_BF16(d, a, b0, b1)                                                           \
    asm volatile("mma.sync.aligned.m16n8k16.row.col.f32.bf16.bf16.f32 "                  \
                 "{%0,%1,%2,%3}, {%4,%5,%6,%7}, {%8,%9}, {%0,%1,%2,%3};"                 \
                 : "+f"((d)[0]), "+f"((d)[1]), "+f"((d)[2]), "+f"((d)[3])                \
                 : "r"((a)[0]), "r"((a)[1]), "r"((a)[2]), "r"((a)[3]), "r"(b0), "r"(b1))
#define CP16(dst, src)                                                                   \
    asm volatile("cp.async.cg.shared.global [%0], [%1], 16;" :: "r"(dst), "l"(src))
#define CPCOMMIT() asm volatile("cp.async.commit_group;")
#define CPWAIT(n)  asm volatile("cp.async.wait_group %0;" :: "n"(n))

__device__ __forceinline__ uint32_t smem_u32(const void* p) {
    uint32_t a;
    asm("{ .reg .u64 t; cvta.to.shared.u64 t, %1; cvt.u32.u64 %0, t; }" : "=r"(a) : "l"(p));
    return a;
}

// ---------------- split precompute ----------------
__global__ __launch_bounds__(256) void split_x(const float* __restrict__ x) {
    const size_t j = (size_t)blockIdx.x * 256 + threadIdx.x;  // one float4 each
    const size_t m = j >> 6;
    const int c4 = (int)(j & 63) * 4;
    const float4 f = *(const float4*)&x[m * D_DIM + c4];
    __nv_bfloat16 h0 = __float2bfloat16(f.x), h1 = __float2bfloat16(f.y);
    __nv_bfloat16 h2 = __float2bfloat16(f.z), h3 = __float2bfloat16(f.w);
    __nv_bfloat16 l0 = __float2bfloat16(f.x - __bfloat162float(h0));
    __nv_bfloat16 l1 = __float2bfloat16(f.y - __bfloat162float(h1));
    __nv_bfloat16 l2 = __float2bfloat16(f.z - __bfloat162float(h2));
    __nv_bfloat16 l3 = __float2bfloat16(f.w - __bfloat162float(h3));
    __nv_bfloat162 H0(h0, h1), H1(h2, h3), L0(l0, l1), L1(l2, l3);
    uint2 hv = make_uint2(*(uint32_t*)&H0, *(uint32_t*)&H1);
    uint2 lv = make_uint2(*(uint32_t*)&L0, *(uint32_t*)&L1);
    *(uint2*)&g_xs[m * 512 + c4] = hv;
    *(uint2*)&g_xs[m * 512 + 256 + c4] = lv;
}

__global__ __launch_bounds__(256) void split_w(const float* __restrict__ W) {
    const int i = blockIdx.x * 256 + threadIdx.x;  // 131072 elems
    const int k = i >> 9, n = i & 511;
    const float f = W[(size_t)k * O_DIM + n];
    __nv_bfloat16 h = __float2bfloat16(f);
    __nv_bfloat16 l = __float2bfloat16(f - __bfloat162float(h));
    g_ws[(size_t)k * 512 + n] = h;
    g_ws[(size_t)(256 + k) * 512 + n] = l;
}

// ---------------- GEMM: tile 128x128, BK=32, double-buffered cp.async ----------------
#define ASTR 40
#define BSTR 136
#define OFF_AL 10240
#define OFF_B  20480
#define OFF_BL 8704
#define STAGE  37888
#define SMEM_DYN 75776  // 2 stages; also >= 128*132*4 transpose buffer

__global__ __launch_bounds__(512) void caps_gemm() {
    extern __shared__ char sm[];
    const uint32_t smb = smem_u32(sm);
    const int tid = threadIdx.x;
    const int wid = tid >> 5, lane = tid & 31;
    const int wm = wid >> 2, wn = wid & 3;
    const int m0 = blockIdx.y * 128;
    const int n0 = blockIdx.x * 128;

    // cp.async assignments
    const int arow = tid >> 2, aq = tid & 3;      // A: 128 x 32
    const int brow = tid >> 4, bg = tid & 15;     // B: 32 x 128
    const uint64_t srcAh0 = __cvta_generic_to_global(&g_xs[(size_t)(m0 + arow) * 512 + aq * 8]);
    const uint64_t srcAl0 = srcAh0 + 256 * 2;
    const uint64_t srcBh0 = __cvta_generic_to_global(&g_ws[(size_t)brow * 512 + n0 + bg * 8]);
    const uint64_t srcBl0 = srcBh0 + (size_t)256 * 512 * 2;
    const uint32_t dstA = smb + (uint32_t)(arow * ASTR + aq * 8) * 2;
    const uint32_t dstB = smb + OFF_B + (uint32_t)(brow * BSTR + bg * 8) * 2;

    // ldmatrix per-lane offsets (within stage regions)
    const int mat = lane >> 3, r = lane & 7;
    uint32_t a_off[2], b_off[2];
#pragma unroll
    for (int fm = 0; fm < 2; fm++)
        a_off[fm] = (uint32_t)(((wm * 32 + fm * 16 + (mat & 1) * 8 + r) * ASTR + (mat >> 1) * 8) * 2);
#pragma unroll
    for (int nf2 = 0; nf2 < 2; nf2++)
        b_off[nf2] = (uint32_t)((((mat & 1) * 8 + r) * BSTR + (mat >> 1) * 8 + wn * 32 + nf2 * 16) * 2);

    float acc[2][4][4];
#pragma unroll
    for (int i = 0; i < 2; i++)
#pragma unroll
        for (int j = 0; j < 4; j++)
#pragma unroll
            for (int k = 0; k < 4; k++) acc[i][j][k] = 0.f;

#define ISSUE(kc) do {                                                     \
        const uint32_t bb = ((kc) & 1) * STAGE;                            \
        const uint64_t ko = (uint64_t)(kc) * 32 * 2;                       \
        CP16(dstA + bb, srcAh0 + ko);                                      \
        CP16(dstA + bb + OFF_AL, srcAl0 + ko);                             \
        const uint64_t kr = (uint64_t)(kc) * 32 * 512 * 2;                 \
        CP16(dstB + bb, srcBh0 + kr);                                      \
        CP16(dstB + bb + OFF_BL, srcBl0 + kr);                             \
        CPCOMMIT();                                                        \
    } while (0)

    ISSUE(0);
    for (int kc = 0; kc < 8; kc++) {
        if (kc < 7) { ISSUE(kc + 1); CPWAIT(1); } else { CPWAIT(0); }
        __syncthreads();
        const uint32_t sb = smb + (kc & 1) * STAGE;
#pragma unroll
        for (int ks = 0; ks < 2; ks++) {
            uint32_t Ah[2][4], Al[2][4];
#pragma unroll
            for (int fm = 0; fm < 2; fm++) {
                LDMX4(Ah[fm], sb + a_off[fm] + ks * 32);
                LDMX4(Al[fm], sb + OFF_AL + a_off[fm] + ks * 32);
            }
#pragma unroll
            for (int nf2 = 0; nf2 < 2; nf2++) {
                uint32_t Bh[4], Bl[4];
                LDMX4T(Bh, sb + OFF_B + b_off[nf2] + ks * 16 * BSTR * 2);
                LDMX4T(Bl, sb + OFF_B + OFF_BL + b_off[nf2] + ks * 16 * BSTR * 2);
#pragma unroll
                for (int fm = 0; fm < 2; fm++) {
                    const int fn = nf2 * 2;
                    MMA_BF16(acc[fm][fn], Ah[fm], Bh[0], Bh[1]);
                    MMA_BF16(acc[fm][fn], Ah[fm], Bl[0], Bl[1]);
                    MMA_BF16(acc[fm][fn], Al[fm], Bh[0], Bh[1]);
                    MMA_BF16(acc[fm][fn + 1], Ah[fm], Bh[2], Bh[3]);
                    MMA_BF16(acc[fm][fn + 1], Ah[fm], Bl[2], Bl[3]);
                    MMA_BF16(acc[fm][fn + 1], Al[fm], Bh[2], Bh[3]);
                }
            }
        }
        __syncthreads();
    }

    // ---- epilogue: transpose in smem, write u_t[b][o][s] ----
    float* smt = (float*)sm;  // [128 o][132 pad] floats
#pragma unroll
    for (int fm = 0; fm < 2; fm++) {
        const int sl = wm * 32 + fm * 16 + (lane >> 2);
#pragma unroll
        for (int fn = 0; fn < 4; fn++) {
            const int oc = wn * 32 + fn * 8 + (lane & 3) * 2;
            smt[oc * 132 + sl] = acc[fm][fn][0];
            smt[(oc + 1) * 132 + sl] = acc[fm][fn][1];
            smt[oc * 132 + sl + 8] = acc[fm][fn][2];
            smt[(oc + 1) * 132 + sl + 8] = acc[fm][fn][3];
        }
    }
    __syncthreads();
    const int b = m0 >> 9;
    const int sbase = m0 & 511;
    const int ol = tid >> 2, seg = tid & 3;
    float* dst = &g_uhat[((size_t)b * 512 + n0 + ol) * 512 + sbase + seg * 32];
    const float* srcT = &smt[ol * 132 + seg * 32];
#pragma unroll
    for (int j = 0; j < 8; j++)
        *(float4*)&dst[j * 4] = *(const float4*)&srcT[j * 4];
}

// ---------------- Routing on u_t[b][o][s]: warp = capsule, lane = s ----------------
__global__ __launch_bounds__(512) void caps_routing(float* __restrict__ out) {
    __shared__ float outsm[O_DIM];
    __shared__ float bsm[NC][33];
    __shared__ float csm[32][17];
    const int bidx = blockIdx.x;
    const int lane = threadIdx.x & 31;
    const int w = threadIdx.x >> 5;  // capsule n
    const float* __restrict__ u = g_uhat + (size_t)bidx * O_DIM * S_DIM + (size_t)w * 32 * S_DIM + lane;

    float acc[32];

    // ---- pass 0: uniform coupling ----
#pragma unroll
    for (int r2 = 0; r2 < 32; r2++) acc[r2] = 0.f;
    for (int chunk = 0; chunk < 16; chunk++) {
        const float* up = u + chunk * 32;
#pragma unroll
        for (int r2 = 0; r2 < 32; r2++) acc[r2] += up[(size_t)r2 * S_DIM];
    }
    {
        float myv = 0.f;
#pragma unroll
        for (int r2 = 0; r2 < 32; r2++) {
            float t = acc[r2];
#pragma unroll
            for (int o = 16; o > 0; o >>= 1) t += __shfl_xor_sync(0xffffffffu, t, o);
            if (lane == r2) myv = t;
        }
        myv *= (1.f / 16.f);
        float ss = myv * myv;
#pragma unroll
        for (int o = 16; o > 0; o >>= 1) ss += __shfl_xor_sync(0xffffffffu, ss, o);
        outsm[w * 32 + lane] = myv / sqrtf(ss + 1e-7f);
    }

    // ---- passes 1,2 ----
    for (int it = 1; it < 3; it++) {
        __syncthreads();  // outsm ready
#pragma unroll
        for (int r2 = 0; r2 < 32; r2++) acc[r2] = 0.f;

        for (int chunk = 0; chunk < 16; chunk++) {
            const float* up = u + chunk * 32;
            float val[32];
#pragma unroll
            for (int r2 = 0; r2 < 32; r2++) val[r2] = up[(size_t)r2 * S_DIM];

            float bl = 0.f;
#pragma unroll
            for (int r2 = 0; r2 < 32; r2++) bl += outsm[w * 32 + r2] * val[r2];
            bsm[w][lane] = bl;
            __syncthreads();

            // softmax for s pair {2w, 2w+1}; lane = n + 16*sp
            {
                const int sp = lane >> 4, n = lane & 15;
                const float bv = bsm[n][2 * w + sp];
                float mx = bv;
#pragma unroll
                for (int o = 8; o > 0; o >>= 1) mx = fmaxf(mx, __shfl_xor_sync(0xffffffffu, mx, o));
                const float e = __expf(bv - mx);
                float den = e;
#pragma unroll
                for (int o = 8; o > 0; o >>= 1) den += __shfl_xor_sync(0xffffffffu, den, o);
                csm[2 * w + sp][n] = e / den;
            }
            __syncthreads();

            const float cw = csm[lane][w];
#pragma unroll
            for (int r2 = 0; r2 < 32; r2++) acc[r2] += cw * val[r2];
        }

        float myv = 0.f;
#pragma unroll
        for (int r2 = 0; r2 < 32; r2++) {
            float t = acc[r2];
#pragma unroll
            for (int o = 16; o > 0; o >>= 1) t += __shfl_xor_sync(0xffffffffu, t, o);
            if (lane == r2) myv = t;
        }
        float ss = myv * myv;
#pragma unroll
        for (int o = 16; o > 0; o >>= 1) ss += __shfl_xor_sync(0xffffffffu, ss, o);
        const float res = myv / sqrtf(ss + 1e-7f);
        if (it == 2) out[(size_t)bidx * O_DIM + w * 32 + lane] = res;
        else outsm[w * 32 + lane] = res;
    }
}

extern "C" void kernel_launch(void* const* d_in, const int* in_sizes, int n_in,
                              void* d_out, int out_size) {
    const float* x = (const float*)d_in[0];
    const float* W = (const float*)d_in[1];
    float* out = (float*)d_out;

    split_x<<<32768, 256>>>(x);          // M*64 float4s
    split_w<<<512, 256>>>(W);
    cudaFuncSetAttribute(caps_gemm, cudaFuncAttributeMaxDynamicSharedMemorySize, SMEM_DYN);
    dim3 grid(O_DIM / 128, M_DIM / 128);  // (4, 1024)
    caps_gemm<<<grid, 512, SMEM_DYN>>>();
    caps_routing<<<B_DIM, 512>>>(out);
}

// round 5
// speedup vs baseline: 1.7902x; 1.0731x over previous
#include <cuda_runtime.h>
#include <cuda_bf16.h>
#include <cstdint>

#define NC 16
#define DC 32
#define S_DIM 512
#define D_DIM 256
#define O_DIM 512
#define B_DIM 256
#define M_DIM (B_DIM * S_DIM)  // 131072

// u_hat TRANSPOSED: [b][o][s]
__device__ float g_uhat[(size_t)B_DIM * O_DIM * S_DIM];
__device__ float g_colsum[(size_t)B_DIM * O_DIM];
// bf16 splits: xs[m][0..255]=hi, [256..511]=lo ; ws rows 0..255 hi, 256..511 lo
__device__ __nv_bfloat16 g_xs[(size_t)M_DIM * 512];
__device__ __nv_bfloat16 g_ws[512 * 512];

// ---------------- PTX helpers ----------------
#define LDMX4(r, addr)                                                                   \
    asm volatile("ldmatrix.sync.aligned.m8n8.x4.shared.b16 {%0,%1,%2,%3}, [%4];"         \
                 : "=r"((r)[0]), "=r"((r)[1]), "=r"((r)[2]), "=r"((r)[3]) : "r"(addr))
#define LDMX4T(r, addr)                                                                  \
    asm volatile("ldmatrix.sync.aligned.m8n8.x4.trans.shared.b16 {%0,%1,%2,%3}, [%4];"   \
                 : "=r"((r)[0]), "=r"((r)[1]), "=r"((r)[2]), "=r"((r)[3]) : "r"(addr))
#define MMA_BF16(d, a, b0, b1)                                                           \
    asm volatile("mma.sync.aligned.m16n8k16.row.col.f32.bf16.bf16.f32 "                  \
                 "{%0,%1,%2,%3}, {%4,%5,%6,%7}, {%8,%9}, {%0,%1,%2,%3};"                 \
                 : "+f"((d)[0]), "+f"((d)[1]), "+f"((d)[2]), "+f"((d)[3])                \
                 : "r"((a)[0]), "r"((a)[1]), "r"((a)[2]), "r"((a)[3]), "r"(b0), "r"(b1))
#define CP16(dst, src)                                                                   \
    asm volatile("cp.async.cg.shared.global [%0], [%1], 16;" :: "r"(dst), "l"(src))
#define CPCOMMIT() asm volatile("cp.async.commit_group;")
#define CPWAIT(n)  asm volatile("cp.async.wait_group %0;" :: "n"(n))

__device__ __forceinline__ uint32_t smem_u32(const void* p) {
    uint32_t a;
    asm("{ .reg .u64 t; cvta.to.shared.u64 t, %1; cvt.u32.u64 %0, t; }" : "=r"(a) : "l"(p));
    return a;
}

// ---------------- split precompute ----------------
__global__ __launch_bounds__(256) void split_x(const float* __restrict__ x) {
    const size_t j = (size_t)blockIdx.x * 256 + threadIdx.x;
    const size_t m = j >> 6;
    const int c4 = (int)(j & 63) * 4;
    const float4 f = *(const float4*)&x[m * D_DIM + c4];
    __nv_bfloat16 h0 = __float2bfloat16(f.x), h1 = __float2bfloat16(f.y);
    __nv_bfloat16 h2 = __float2bfloat16(f.z), h3 = __float2bfloat16(f.w);
    __nv_bfloat16 l0 = __float2bfloat16(f.x - __bfloat162float(h0));
    __nv_bfloat16 l1 = __float2bfloat16(f.y - __bfloat162float(h1));
    __nv_bfloat16 l2 = __float2bfloat16(f.z - __bfloat162float(h2));
    __nv_bfloat16 l3 = __float2bfloat16(f.w - __bfloat162float(h3));
    __nv_bfloat162 H0(h0, h1), H1(h2, h3), L0(l0, l1), L1(l2, l3);
    *(uint2*)&g_xs[m * 512 + c4] = make_uint2(*(uint32_t*)&H0, *(uint32_t*)&H1);
    *(uint2*)&g_xs[m * 512 + 256 + c4] = make_uint2(*(uint32_t*)&L0, *(uint32_t*)&L1);
}

__global__ __launch_bounds__(256) void split_w(const float* __restrict__ W) {
    const int i = blockIdx.x * 256 + threadIdx.x;
    const int k = i >> 9, n = i & 511;
    const float f = W[(size_t)k * O_DIM + n];
    __nv_bfloat16 h = __float2bfloat16(f);
    __nv_bfloat16 l = __float2bfloat16(f - __bfloat162float(h));
    g_ws[(size_t)k * 512 + n] = h;
    g_ws[(size_t)(256 + k) * 512 + n] = l;
}

__global__ __launch_bounds__(512) void zero_colsum() {
    g_colsum[(size_t)blockIdx.x * 512 + threadIdx.x] = 0.f;
}

// ---------------- GEMM: tile 128x64, BK=32, 256 threads, 2 CTAs/SM ----------------
#define ASTR 40
#define BSTR 72
#define OFF_AL 10240   // 128*40*2
#define OFF_B  20480
#define OFF_BL 25088   // +32*72*2
#define STAGE  29696
#define SMEM_DYN 59392 // 2 stages; also >= 64*132*4 transpose buffer

__global__ __launch_bounds__(256, 2) void caps_gemm() {
    extern __shared__ char sm[];
    const uint32_t smb = smem_u32(sm);
    const int tid = threadIdx.x;
    const int wid = tid >> 5, lane = tid & 31;
    const int wm = wid >> 1, wn = wid & 1;   // 4x2 warps, warp tile 32x32
    const int m0 = blockIdx.y * 128;
    const int n0 = blockIdx.x * 64;

    // cp.async source/dest
    const int arow = tid >> 1, ahalf = tid & 1;     // A: 128 rows x 2 halves of 16
    const int brow = tid >> 3, bg = tid & 7;        // B: 32 rows x 8 groups of 8
    const uint64_t srcAh = __cvta_generic_to_global(&g_xs[(size_t)(m0 + arow) * 512 + ahalf * 16]);
    const uint64_t srcAl = srcAh + 256 * 2;
    const uint64_t srcBh = __cvta_generic_to_global(&g_ws[(size_t)brow * 512 + n0 + bg * 8]);
    const uint64_t srcBl = srcBh + (size_t)256 * 512 * 2;
    const uint32_t dstA = smb + (uint32_t)(arow * ASTR + ahalf * 16) * 2;
    const uint32_t dstB = smb + OFF_B + (uint32_t)(brow * BSTR + bg * 8) * 2;

    // ldmatrix per-lane offsets
    const int mat = lane >> 3, r = lane & 7;
    uint32_t a_off[2], b_off[2];
#pragma unroll
    for (int fm = 0; fm < 2; fm++)
        a_off[fm] = (uint32_t)(((wm * 32 + fm * 16 + (mat & 1) * 8 + r) * ASTR + (mat >> 1) * 8) * 2);
#pragma unroll
    for (int nf2 = 0; nf2 < 2; nf2++)
        b_off[nf2] = (uint32_t)((((mat & 1) * 8 + r) * BSTR + (mat >> 1) * 8 + wn * 32 + nf2 * 16) * 2);

    float acc[2][4][4];
#pragma unroll
    for (int i = 0; i < 2; i++)
#pragma unroll
        for (int j = 0; j < 4; j++)
#pragma unroll
            for (int k = 0; k < 4; k++) acc[i][j][k] = 0.f;

#define ISSUE(kc) do {                                                     \
        const uint32_t bb = ((kc) & 1) * STAGE;                            \
        const uint64_t ka = (uint64_t)(kc) * 64;                           \
        CP16(dstA + bb, srcAh + ka); CP16(dstA + bb + 16, srcAh + ka + 16);\
        CP16(dstA + bb + OFF_AL, srcAl + ka);                              \
        CP16(dstA + bb + OFF_AL + 16, srcAl + ka + 16);                    \
        const uint64_t kb = (uint64_t)(kc) * 32768;                        \
        CP16(dstB + bb, srcBh + kb);                                       \
        CP16(dstB + bb + (OFF_BL - OFF_B), srcBl + kb);                    \
        CPCOMMIT();                                                        \
    } while (0)

    ISSUE(0);
    for (int kc = 0; kc < 8; kc++) {
        if (kc < 7) { ISSUE(kc + 1); CPWAIT(1); } else { CPWAIT(0); }
        __syncthreads();
        const uint32_t sb = smb + (kc & 1) * STAGE;
#pragma unroll
        for (int ks = 0; ks < 2; ks++) {
            uint32_t Ah[2][4], Al[2][4];
#pragma unroll
            for (int fm = 0; fm < 2; fm++) {
                LDMX4(Ah[fm], sb + a_off[fm] + ks * 32);
                LDMX4(Al[fm], sb + OFF_AL + a_off[fm] + ks * 32);
            }
#pragma unroll
            for (int nf2 = 0; nf2 < 2; nf2++) {
                uint32_t Bh[4], Bl[4];
                LDMX4T(Bh, sb + OFF_B + b_off[nf2] + ks * 16 * BSTR * 2);
                LDMX4T(Bl, sb + OFF_BL + b_off[nf2] + ks * 16 * BSTR * 2);
#pragma unroll
                for (int fm = 0; fm < 2; fm++) {
                    const int fn = nf2 * 2;
                    MMA_BF16(acc[fm][fn], Ah[fm], Bh[0], Bh[1]);
                    MMA_BF16(acc[fm][fn], Ah[fm], Bl[0], Bl[1]);
                    MMA_BF16(acc[fm][fn], Al[fm], Bh[0], Bh[1]);
                    MMA_BF16(acc[fm][fn + 1], Ah[fm], Bh[2], Bh[3]);
                    MMA_BF16(acc[fm][fn + 1], Ah[fm], Bl[2], Bl[3]);
                    MMA_BF16(acc[fm][fn + 1], Al[fm], Bh[2], Bh[3]);
                }
            }
        }
        __syncthreads();
    }

    // ---- epilogue: transpose in smem, write u_t[b][o][s], fused column sums ----
    float* smt = (float*)sm;  // [64 o][132 pad]
#pragma unroll
    for (int fm = 0; fm < 2; fm++) {
        const int sl = wm * 32 + fm * 16 + (lane >> 2);
#pragma unroll
        for (int fn = 0; fn < 4; fn++) {
            const int oc = wn * 32 + fn * 8 + (lane & 3) * 2;
            smt[oc * 132 + sl] = acc[fm][fn][0];
            smt[(oc + 1) * 132 + sl] = acc[fm][fn][1];
            smt[oc * 132 + sl + 8] = acc[fm][fn][2];
            smt[(oc + 1) * 132 + sl + 8] = acc[fm][fn][3];
        }
    }
    __syncthreads();
    const int b = m0 >> 9;
    const int sbase = m0 & 511;
    const int ol = tid >> 2, seg = tid & 3;
    float* dst = &g_uhat[((size_t)b * 512 + n0 + ol) * 512 + sbase + seg * 32];
    const float* srcT = &smt[ol * 132 + seg * 32];
    float csum = 0.f;
#pragma unroll
    for (int j = 0; j < 8; j++) {
        const float4 v = *(const float4*)&srcT[j * 4];
        csum += (v.x + v.y) + (v.z + v.w);
        *(float4*)&dst[j * 4] = v;
    }
    atomicAdd(&g_colsum[(size_t)b * 512 + n0 + ol], csum);
}

// ---------------- Routing: passes 1,2 only (pass 0 fused into GEMM) ----------------
__global__ __launch_bounds__(512) void caps_routing(float* __restrict__ out) {
    __shared__ float outsm[O_DIM];
    __shared__ float bsm[NC][33];
    __shared__ float csm[32][17];
    const int bidx = blockIdx.x;
    const int lane = threadIdx.x & 31;
    const int w = threadIdx.x >> 5;  // capsule n
    const float* __restrict__ u =
        g_uhat + (size_t)bidx * O_DIM * S_DIM + (size_t)w * 32 * S_DIM + lane;

    // pass 0 result from fused column sums
    {
        const float myv = g_colsum[(size_t)bidx * 512 + threadIdx.x] * (1.f / 16.f);
        float ss = myv * myv;
#pragma unroll
        for (int o = 16; o > 0; o >>= 1) ss += __shfl_xor_sync(0xffffffffu, ss, o);
        outsm[threadIdx.x] = myv / sqrtf(ss + 1e-7f);
    }

    float acc[32];
    for (int it = 1; it < 3; it++) {
        __syncthreads();
#pragma unroll
        for (int r2 = 0; r2 < 32; r2++) acc[r2] = 0.f;

        for (int chunk = 0; chunk < 16; chunk++) {
            const float* up = u + chunk * 32;
            float val[32];
#pragma unroll
            for (int r2 = 0; r2 < 32; r2++) val[r2] = up[(size_t)r2 * S_DIM];

            float bl = 0.f;
#pragma unroll
            for (int r2 = 0; r2 < 32; r2++) bl += outsm[w * 32 + r2] * val[r2];
            bsm[w][lane] = bl;
            __syncthreads();

            {
                const int sp = lane >> 4, n = lane & 15;
                const float bv = bsm[n][2 * w + sp];
                float mx = bv;
#pragma unroll
                for (int o = 8; o > 0; o >>= 1) mx = fmaxf(mx, __shfl_xor_sync(0xffffffffu, mx, o));
                const float e = __expf(bv - mx);
                float den = e;
#pragma unroll
                for (int o = 8; o > 0; o >>= 1) den += __shfl_xor_sync(0xffffffffu, den, o);
                csm[2 * w + sp][n] = e / den;
            }
            __syncthreads();

            const float cw = csm[lane][w];
#pragma unroll
            for (int r2 = 0; r2 < 32; r2++) acc[r2] += cw * val[r2];
        }

        float myv = 0.f;
#pragma unroll
        for (int r2 = 0; r2 < 32; r2++) {
            float t = acc[r2];
#pragma unroll
            for (int o = 16; o > 0; o >>= 1) t += __shfl_xor_sync(0xffffffffu, t, o);
            if (lane == r2) myv = t;
        }
        float ss = myv * myv;
#pragma unroll
        for (int o = 16; o > 0; o >>= 1) ss += __shfl_xor_sync(0xffffffffu, ss, o);
        const float res = myv / sqrtf(ss + 1e-7f);
        if (it == 2) out[(size_t)bidx * O_DIM + w * 32 + lane] = res;
        else outsm[w * 32 + lane] = res;
    }
}

extern "C" void kernel_launch(void* const* d_in, const int* in_sizes, int n_in,
                              void* d_out, int out_size) {
    const float* x = (const float*)d_in[0];
    const float* W = (const float*)d_in[1];
    float* out = (float*)d_out;

    split_x<<<32768, 256>>>(x);
    split_w<<<512, 256>>>(W);
    zero_colsum<<<256, 512>>>();
    cudaFuncSetAttribute(caps_gemm, cudaFuncAttributeMaxDynamicSharedMemorySize, SMEM_DYN);
    dim3 grid(O_DIM / 64, M_DIM / 128);  // (8, 1024)
    caps_gemm<<<grid, 256, SMEM_DYN>>>();
    caps_routing<<<B_DIM, 512>>>(out);
}

// round 6
// speedup vs baseline: 1.8097x; 1.0109x over previous
#include <cuda_runtime.h>
#include <cuda_bf16.h>
#include <cstdint>

#define NC 16
#define DC 32
#define S_DIM 512
#define D_DIM 256
#define O_DIM 512
#define B_DIM 256
#define M_DIM (B_DIM * S_DIM)  // 131072

// u_hat TRANSPOSED: [b][o][s]
__device__ float g_uhat[(size_t)B_DIM * O_DIM * S_DIM];
__device__ float g_colsum[(size_t)B_DIM * O_DIM];
// bf16 splits: xs[m][0..255]=hi, [256..511]=lo ; ws rows 0..255 hi, 256..511 lo
__device__ __nv_bfloat16 g_xs[(size_t)M_DIM * 512];
__device__ __nv_bfloat16 g_ws[512 * 512];

// ---------------- PTX helpers ----------------
#define LDMX4(r, addr)                                                                   \
    asm volatile("ldmatrix.sync.aligned.m8n8.x4.shared.b16 {%0,%1,%2,%3}, [%4];"         \
                 : "=r"((r)[0]), "=r"((r)[1]), "=r"((r)[2]), "=r"((r)[3]) : "r"(addr))
#define LDMX4T(r, addr)                                                                  \
    asm volatile("ldmatrix.sync.aligned.m8n8.x4.trans.shared.b16 {%0,%1,%2,%3}, [%4];"   \
                 : "=r"((r)[0]), "=r"((r)[1]), "=r"((r)[2]), "=r"((r)[3]) : "r"(addr))
#define MMA_BF16(d, a, b0, b1)                                                           \
    asm volatile("mma.sync.aligned.m16n8k16.row.col.f32.bf16.bf16.f32 "                  \
                 "{%0,%1,%2,%3}, {%4,%5,%6,%7}, {%8,%9}, {%0,%1,%2,%3};"                 \
                 : "+f"((d)[0]), "+f"((d)[1]), "+f"((d)[2]), "+f"((d)[3])                \
                 : "r"((a)[0]), "r"((a)[1]), "r"((a)[2]), "r"((a)[3]), "r"(b0), "r"(b1))
#define CP16(dst, src)                                                                   \
    asm volatile("cp.async.cg.shared.global [%0], [%1], 16;" :: "r"(dst), "l"(src))
#define CPCOMMIT() asm volatile("cp.async.commit_group;")
#define CPWAIT(n)  asm volatile("cp.async.wait_group %0;" :: "n"(n))

__device__ __forceinline__ uint32_t smem_u32(const void* p) {
    uint32_t a;
    asm("{ .reg .u64 t; cvta.to.shared.u64 t, %1; cvt.u32.u64 %0, t; }" : "=r"(a) : "l"(p));
    return a;
}

// ---------------- split precompute ----------------
__global__ __launch_bounds__(256) void split_x(const float* __restrict__ x) {
    const size_t j = (size_t)blockIdx.x * 256 + threadIdx.x;
    const size_t m = j >> 6;
    const int c4 = (int)(j & 63) * 4;
    const float4 f = *(const float4*)&x[m * D_DIM + c4];
    __nv_bfloat16 h0 = __float2bfloat16(f.x), h1 = __float2bfloat16(f.y);
    __nv_bfloat16 h2 = __float2bfloat16(f.z), h3 = __float2bfloat16(f.w);
    __nv_bfloat16 l0 = __float2bfloat16(f.x - __bfloat162float(h0));
    __nv_bfloat16 l1 = __float2bfloat16(f.y - __bfloat162float(h1));
    __nv_bfloat16 l2 = __float2bfloat16(f.z - __bfloat162float(h2));
    __nv_bfloat16 l3 = __float2bfloat16(f.w - __bfloat162float(h3));
    __nv_bfloat162 H0(h0, h1), H1(h2, h3), L0(l0, l1), L1(l2, l3);
    *(uint2*)&g_xs[m * 512 + c4] = make_uint2(*(uint32_t*)&H0, *(uint32_t*)&H1);
    *(uint2*)&g_xs[m * 512 + 256 + c4] = make_uint2(*(uint32_t*)&L0, *(uint32_t*)&L1);
}

__global__ __launch_bounds__(256) void split_w(const float* __restrict__ W) {
    const int i = blockIdx.x * 256 + threadIdx.x;
    const int k = i >> 9, n = i & 511;
    const float f = W[(size_t)k * O_DIM + n];
    __nv_bfloat16 h = __float2bfloat16(f);
    __nv_bfloat16 l = __float2bfloat16(f - __bfloat162float(h));
    g_ws[(size_t)k * 512 + n] = h;
    g_ws[(size_t)(256 + k) * 512 + n] = l;
}

__global__ __launch_bounds__(512) void zero_colsum() {
    g_colsum[(size_t)blockIdx.x * 512 + threadIdx.x] = 0.f;
}

// ---------------- GEMM: tile 128x64, BK=32, 256 threads, 3-stage pipeline ----------------
#define ASTR 40
#define BSTR 72
#define OFF_AL 10240   // 128*40*2
#define OFF_B  20480
#define OFF_BL 25088   // +32*72*2
#define STAGE  29696
#define SMEM_DYN (3 * STAGE)  // 89088; also >= 64*132*4 transpose buffer

__global__ __launch_bounds__(256, 2) void caps_gemm() {
    extern __shared__ char sm[];
    const uint32_t smb = smem_u32(sm);
    const int tid = threadIdx.x;
    const int wid = tid >> 5, lane = tid & 31;
    const int wm = wid >> 1, wn = wid & 1;   // 4x2 warps, warp tile 32x32
    const int m0 = blockIdx.y * 128;
    const int n0 = blockIdx.x * 64;

    // cp.async source/dest
    const int arow = tid >> 1, ahalf = tid & 1;     // A: 128 rows x 2 halves of 16
    const int brow = tid >> 3, bg = tid & 7;        // B: 32 rows x 8 groups of 8
    const uint64_t srcAh = __cvta_generic_to_global(&g_xs[(size_t)(m0 + arow) * 512 + ahalf * 16]);
    const uint64_t srcAl = srcAh + 256 * 2;
    const uint64_t srcBh = __cvta_generic_to_global(&g_ws[(size_t)brow * 512 + n0 + bg * 8]);
    const uint64_t srcBl = srcBh + (size_t)256 * 512 * 2;
    const uint32_t dstA = smb + (uint32_t)(arow * ASTR + ahalf * 16) * 2;
    const uint32_t dstB = smb + OFF_B + (uint32_t)(brow * BSTR + bg * 8) * 2;

    // ldmatrix per-lane offsets
    const int mat = lane >> 3, r = lane & 7;
    uint32_t a_off[2], b_off[2];
#pragma unroll
    for (int fm = 0; fm < 2; fm++)
        a_off[fm] = (uint32_t)(((wm * 32 + fm * 16 + (mat & 1) * 8 + r) * ASTR + (mat >> 1) * 8) * 2);
#pragma unroll
    for (int nf2 = 0; nf2 < 2; nf2++)
        b_off[nf2] = (uint32_t)((((mat & 1) * 8 + r) * BSTR + (mat >> 1) * 8 + wn * 32 + nf2 * 16) * 2);

    float acc[2][4][4];
#pragma unroll
    for (int i = 0; i < 2; i++)
#pragma unroll
        for (int j = 0; j < 4; j++)
#pragma unroll
            for (int k = 0; k < 4; k++) acc[i][j][k] = 0.f;

#define ISSUE(kc) do {                                                     \
        const uint32_t bb = ((kc) % 3) * STAGE;                            \
        const uint64_t ka = (uint64_t)(kc) * 64;                           \
        CP16(dstA + bb, srcAh + ka); CP16(dstA + bb + 16, srcAh + ka + 16);\
        CP16(dstA + bb + OFF_AL, srcAl + ka);                              \
        CP16(dstA + bb + OFF_AL + 16, srcAl + ka + 16);                    \
        const uint64_t kb = (uint64_t)(kc) * 32768;                        \
        CP16(dstB + bb, srcBh + kb);                                       \
        CP16(dstB + bb + (OFF_BL - OFF_B), srcBl + kb);                    \
        CPCOMMIT();                                                        \
    } while (0)

    // 3-stage multistage pipeline: one sync per chunk, prefetch distance 2.
    ISSUE(0);
    ISSUE(1);
#pragma unroll
    for (int kc = 0; kc < 8; kc++) {
        if (kc < 7) { CPWAIT(1); } else { CPWAIT(0); }
        __syncthreads();
        if (kc < 6) ISSUE(kc + 2);

        const uint32_t sb = smb + (kc % 3) * STAGE;
#pragma unroll
        for (int ks = 0; ks < 2; ks++) {
            uint32_t Ah[2][4], Al[2][4];
#pragma unroll
            for (int fm = 0; fm < 2; fm++) {
                LDMX4(Ah[fm], sb + a_off[fm] + ks * 32);
                LDMX4(Al[fm], sb + OFF_AL + a_off[fm] + ks * 32);
            }
#pragma unroll
            for (int nf2 = 0; nf2 < 2; nf2++) {
                uint32_t Bh[4], Bl[4];
                LDMX4T(Bh, sb + OFF_B + b_off[nf2] + ks * 16 * BSTR * 2);
                LDMX4T(Bl, sb + OFF_BL + b_off[nf2] + ks * 16 * BSTR * 2);
#pragma unroll
                for (int fm = 0; fm < 2; fm++) {
                    const int fn = nf2 * 2;
                    MMA_BF16(acc[fm][fn], Ah[fm], Bh[0], Bh[1]);
                    MMA_BF16(acc[fm][fn], Ah[fm], Bl[0], Bl[1]);
                    MMA_BF16(acc[fm][fn], Al[fm], Bh[0], Bh[1]);
                    MMA_BF16(acc[fm][fn + 1], Ah[fm], Bh[2], Bh[3]);
                    MMA_BF16(acc[fm][fn + 1], Ah[fm], Bl[2], Bl[3]);
                    MMA_BF16(acc[fm][fn + 1], Al[fm], Bh[2], Bh[3]);
                }
            }
        }
    }
    __syncthreads();  // stage buffers re-purposed as transpose scratch below

    // ---- epilogue: transpose in smem, write u_t[b][o][s], fused column sums ----
    float* smt = (float*)sm;  // [64 o][132 pad]
#pragma unroll
    for (int fm = 0; fm < 2; fm++) {
        const int sl = wm * 32 + fm * 16 + (lane >> 2);
#pragma unroll
        for (int fn = 0; fn < 4; fn++) {
            const int oc = wn * 32 + fn * 8 + (lane & 3) * 2;
            smt[oc * 132 + sl] = acc[fm][fn][0];
            smt[(oc + 1) * 132 + sl] = acc[fm][fn][1];
            smt[oc * 132 + sl + 8] = acc[fm][fn][2];
            smt[(oc + 1) * 132 + sl + 8] = acc[fm][fn][3];
        }
    }
    __syncthreads();
    const int b = m0 >> 9;
    const int sbase = m0 & 511;
    const int ol = tid >> 2, seg = tid & 3;
    float* dst = &g_uhat[((size_t)b * 512 + n0 + ol) * 512 + sbase + seg * 32];
    const float* srcT = &smt[ol * 132 + seg * 32];
    float csum = 0.f;
#pragma unroll
    for (int j = 0; j < 8; j++) {
        const float4 v = *(const float4*)&srcT[j * 4];
        csum += (v.x + v.y) + (v.z + v.w);
        *(float4*)&dst[j * 4] = v;
    }
    atomicAdd(&g_colsum[(size_t)b * 512 + n0 + ol], csum);
}

// ---------------- Routing: passes 1,2 only (pass 0 fused into GEMM) ----------------
__global__ __launch_bounds__(512) void caps_routing(float* __restrict__ out) {
    __shared__ float outsm[O_DIM];
    __shared__ float bsm[NC][33];
    __shared__ float csm[32][17];
    const int bidx = blockIdx.x;
    const int lane = threadIdx.x & 31;
    const int w = threadIdx.x >> 5;  // capsule n
    const float* __restrict__ u =
        g_uhat + (size_t)bidx * O_DIM * S_DIM + (size_t)w * 32 * S_DIM + lane;

    // pass 0 result from fused column sums
    {
        const float myv = g_colsum[(size_t)bidx * 512 + threadIdx.x] * (1.f / 16.f);
        float ss = myv * myv;
#pragma unroll
        for (int o = 16; o > 0; o >>= 1) ss += __shfl_xor_sync(0xffffffffu, ss, o);
        outsm[threadIdx.x] = myv / sqrtf(ss + 1e-7f);
    }

    float acc[32];
    for (int it = 1; it < 3; it++) {
        __syncthreads();
#pragma unroll
        for (int r2 = 0; r2 < 32; r2++) acc[r2] = 0.f;

        for (int chunk = 0; chunk < 16; chunk++) {
            const float* up = u + chunk * 32;
            float val[32];
#pragma unroll
            for (int r2 = 0; r2 < 32; r2++) val[r2] = up[(size_t)r2 * S_DIM];

            float bl = 0.f;
#pragma unroll
            for (int r2 = 0; r2 < 32; r2++) bl += outsm[w * 32 + r2] * val[r2];
            bsm[w][lane] = bl;
            __syncthreads();

            {
                const int sp = lane >> 4, n = lane & 15;
                const float bv = bsm[n][2 * w + sp];
                float mx = bv;
#pragma unroll
                for (int o = 8; o > 0; o >>= 1) mx = fmaxf(mx, __shfl_xor_sync(0xffffffffu, mx, o));
                const float e = __expf(bv - mx);
                float den = e;
#pragma unroll
                for (int o = 8; o > 0; o >>= 1) den += __shfl_xor_sync(0xffffffffu, den, o);
                csm[2 * w + sp][n] = e / den;
            }
            __syncthreads();

            const float cw = csm[lane][w];
#pragma unroll
            for (int r2 = 0; r2 < 32; r2++) acc[r2] += cw * val[r2];
        }

        float myv = 0.f;
#pragma unroll
        for (int r2 = 0; r2 < 32; r2++) {
            float t = acc[r2];
#pragma unroll
            for (int o = 16; o > 0; o >>= 1) t += __shfl_xor_sync(0xffffffffu, t, o);
            if (lane == r2) myv = t;
        }
        float ss = myv * myv;
#pragma unroll
        for (int o = 16; o > 0; o >>= 1) ss += __shfl_xor_sync(0xffffffffu, ss, o);
        const float res = myv / sqrtf(ss + 1e-7f);
        if (it == 2) out[(size_t)bidx * O_DIM + w * 32 + lane] = res;
        else outsm[w * 32 + lane] = res;
    }
}

extern "C" void kernel_launch(void* const* d_in, const int* in_sizes, int n_in,
                              void* d_out, int out_size) {
    const float* x = (const float*)d_in[0];
    const float* W = (const float*)d_in[1];
    float* out = (float*)d_out;

    split_x<<<32768, 256>>>(x);
    split_w<<<512, 256>>>(W);
    zero_colsum<<<256, 512>>>();
    cudaFuncSetAttribute(caps_gemm, cudaFuncAttributeMaxDynamicSharedMemorySize, SMEM_DYN);
    dim3 grid(O_DIM / 64, M_DIM / 128);  // (8, 1024)
    caps_gemm<<<grid, 256, SMEM_DYN>>>();
    caps_routing<<<B_DIM, 512>>>(out);
}

// round 7
// speedup vs baseline: 1.8182x; 1.0047x over previous
#include <cuda_runtime.h>
#include <cuda_bf16.h>
#include <cstdint>

#define NC 16
#define DC 32
#define S_DIM 512
#define D_DIM 256
#define O_DIM 512
#define B_DIM 256
#define M_DIM (B_DIM * S_DIM)  // 131072

// u_hat TRANSPOSED: [b][o][s]
__device__ float g_uhat[(size_t)B_DIM * O_DIM * S_DIM];
__device__ float g_colsum[(size_t)B_DIM * O_DIM];
__device__ __nv_bfloat16 g_xs[(size_t)M_DIM * 512];
__device__ __nv_bfloat16 g_ws[512 * 512];

// ---------------- PTX helpers ----------------
#define LDMX4(r, addr)                                                                   \
    asm volatile("ldmatrix.sync.aligned.m8n8.x4.shared.b16 {%0,%1,%2,%3}, [%4];"         \
                 : "=r"((r)[0]), "=r"((r)[1]), "=r"((r)[2]), "=r"((r)[3]) : "r"(addr))
#define LDMX4T(r, addr)                                                                  \
    asm volatile("ldmatrix.sync.aligned.m8n8.x4.trans.shared.b16 {%0,%1,%2,%3}, [%4];"   \
                 : "=r"((r)[0]), "=r"((r)[1]), "=r"((r)[2]), "=r"((r)[3]) : "r"(addr))
#define MMA_BF16(d, a, b0, b1)                                                           \
    asm volatile("mma.sync.aligned.m16n8k16.row.col.f32.bf16.bf16.f32 "                  \
                 "{%0,%1,%2,%3}, {%4,%5,%6,%7}, {%8,%9}, {%0,%1,%2,%3};"                 \
                 : "+f"((d)[0]), "+f"((d)[1]), "+f"((d)[2]), "+f"((d)[3])                \
                 : "r"((a)[0]), "r"((a)[1]), "r"((a)[2]), "r"((a)[3]), "r"(b0), "r"(b1))
#define CP16(dst, src)                                                                   \
    asm volatile("cp.async.cg.shared.global [%0], [%1], 16;" :: "r"(dst), "l"(src))
#define CPCOMMIT() asm volatile("cp.async.commit_group;")
#define CPWAIT(n)  asm volatile("cp.async.wait_group %0;" :: "n"(n))

__device__ __forceinline__ uint32_t smem_u32(const void* p) {
    uint32_t a;
    asm("{ .reg .u64 t; cvta.to.shared.u64 t, %1; cvt.u32.u64 %0, t; }" : "=r"(a) : "l"(p));
    return a;
}

// ---------------- split precompute ----------------
__global__ __launch_bounds__(256) void split_x(const float* __restrict__ x) {
    const size_t j = (size_t)blockIdx.x * 256 + threadIdx.x;
    const size_t m = j >> 6;
    const int c4 = (int)(j & 63) * 4;
    const float4 f = *(const float4*)&x[m * D_DIM + c4];
    __nv_bfloat16 h0 = __float2bfloat16(f.x), h1 = __float2bfloat16(f.y);
    __nv_bfloat16 h2 = __float2bfloat16(f.z), h3 = __float2bfloat16(f.w);
    __nv_bfloat16 l0 = __float2bfloat16(f.x - __bfloat162float(h0));
    __nv_bfloat16 l1 = __float2bfloat16(f.y - __bfloat162float(h1));
    __nv_bfloat16 l2 = __float2bfloat16(f.z - __bfloat162float(h2));
    __nv_bfloat16 l3 = __float2bfloat16(f.w - __bfloat162float(h3));
    __nv_bfloat162 H0(h0, h1), H1(h2, h3), L0(l0, l1), L1(l2, l3);
    *(uint2*)&g_xs[m * 512 + c4] = make_uint2(*(uint32_t*)&H0, *(uint32_t*)&H1);
    *(uint2*)&g_xs[m * 512 + 256 + c4] = make_uint2(*(uint32_t*)&L0, *(uint32_t*)&L1);
}

__global__ __launch_bounds__(256) void split_w(const float* __restrict__ W) {
    const int i = blockIdx.x * 256 + threadIdx.x;
    const int k = i >> 9, n = i & 511;
    const float f = W[(size_t)k * O_DIM + n];
    __nv_bfloat16 h = __float2bfloat16(f);
    __nv_bfloat16 l = __float2bfloat16(f - __bfloat162float(h));
    g_ws[(size_t)k * 512 + n] = h;
    g_ws[(size_t)(256 + k) * 512 + n] = l;
}

__global__ __launch_bounds__(512) void zero_colsum() {
    g_colsum[(size_t)blockIdx.x * 512 + threadIdx.x] = 0.f;
}

// ---------------- GEMM: tile 128x64, BK=32, 256 threads, 2 stages, 3 CTAs/SM ----------------
#define ASTR 40
#define BSTR 72
#define OFF_AL 10240   // 128*40*2
#define OFF_B  20480
#define OFF_BL 25088   // +32*72*2
#define STAGE  29696
#define SMEM_DYN (2 * STAGE)  // 59392; also >= 64*132*4 transpose buffer

__global__ __launch_bounds__(256, 3) void caps_gemm() {
    extern __shared__ char sm[];
    const uint32_t smb = smem_u32(sm);
    const int tid = threadIdx.x;
    const int wid = tid >> 5, lane = tid & 31;
    const int wm = wid >> 1, wn = wid & 1;   // 4x2 warps, warp tile 32x32
    const int m0 = blockIdx.y * 128;
    const int n0 = blockIdx.x * 64;

    // cp.async source/dest
    const int arow = tid >> 1, ahalf = tid & 1;
    const int brow = tid >> 3, bg = tid & 7;
    const uint64_t srcAh = __cvta_generic_to_global(&g_xs[(size_t)(m0 + arow) * 512 + ahalf * 16]);
    const uint64_t srcAl = srcAh + 256 * 2;
    const uint64_t srcBh = __cvta_generic_to_global(&g_ws[(size_t)brow * 512 + n0 + bg * 8]);
    const uint64_t srcBl = srcBh + (size_t)256 * 512 * 2;
    const uint32_t dstA = smb + (uint32_t)(arow * ASTR + ahalf * 16) * 2;
    const uint32_t dstB = smb + OFF_B + (uint32_t)(brow * BSTR + bg * 8) * 2;

    // ldmatrix per-lane offsets
    const int mat = lane >> 3, r = lane & 7;
    uint32_t a_off[2], b_off[2];
#pragma unroll
    for (int fm = 0; fm < 2; fm++)
        a_off[fm] = (uint32_t)(((wm * 32 + fm * 16 + (mat & 1) * 8 + r) * ASTR + (mat >> 1) * 8) * 2);
#pragma unroll
    for (int nf2 = 0; nf2 < 2; nf2++)
        b_off[nf2] = (uint32_t)((((mat & 1) * 8 + r) * BSTR + (mat >> 1) * 8 + wn * 32 + nf2 * 16) * 2);

    float acc[2][4][4];
#pragma unroll
    for (int i = 0; i < 2; i++)
#pragma unroll
        for (int j = 0; j < 4; j++)
#pragma unroll
            for (int k = 0; k < 4; k++) acc[i][j][k] = 0.f;

#define ISSUE(kc) do {                                                     \
        const uint32_t bb = ((kc) & 1) * STAGE;                            \
        const uint64_t ka = (uint64_t)(kc) * 64;                           \
        CP16(dstA + bb, srcAh + ka); CP16(dstA + bb + 16, srcAh + ka + 16);\
        CP16(dstA + bb + OFF_AL, srcAl + ka);                              \
        CP16(dstA + bb + OFF_AL + 16, srcAl + ka + 16);                    \
        const uint64_t kb = (uint64_t)(kc) * 32768;                        \
        CP16(dstB + bb, srcBh + kb);                                       \
        CP16(dstB + bb + (OFF_BL - OFF_B), srcBl + kb);                    \
        CPCOMMIT();                                                        \
    } while (0)

    ISSUE(0);
    for (int kc = 0; kc < 8; kc++) {
        if (kc < 7) { ISSUE(kc + 1); CPWAIT(1); } else { CPWAIT(0); }
        __syncthreads();
        const uint32_t sb = smb + (kc & 1) * STAGE;
#pragma unroll
        for (int ks = 0; ks < 2; ks++) {
            // hoist ALL 16 ldmatrix of this ks-step, then 24 MMAs round-robin
            uint32_t Ah[2][4], Al[2][4], Bh[2][4], Bl[2][4];
#pragma unroll
            for (int fm = 0; fm < 2; fm++) {
                LDMX4(Ah[fm], sb + a_off[fm] + ks * 32);
                LDMX4(Al[fm], sb + OFF_AL + a_off[fm] + ks * 32);
            }
#pragma unroll
            for (int nf2 = 0; nf2 < 2; nf2++) {
                LDMX4T(Bh[nf2], sb + OFF_B + b_off[nf2] + ks * 16 * BSTR * 2);
                LDMX4T(Bl[nf2], sb + OFF_BL + b_off[nf2] + ks * 16 * BSTR * 2);
            }
            // variant-major: consecutive MMAs hit distinct accumulators
#pragma unroll
            for (int v = 0; v < 3; v++)
#pragma unroll
                for (int nf2 = 0; nf2 < 2; nf2++)
#pragma unroll
                    for (int fm = 0; fm < 2; fm++)
#pragma unroll
                        for (int h = 0; h < 2; h++) {
                            const uint32_t* Af = (v == 2) ? Al[fm] : Ah[fm];
                            const uint32_t* Bf = (v == 1) ? Bl[nf2] : Bh[nf2];
                            MMA_BF16(acc[fm][nf2 * 2 + h], Af, Bf[h * 2], Bf[h * 2 + 1]);
                        }
        }
        __syncthreads();
    }

    // ---- epilogue: transpose in smem, write u_t[b][o][s], fused column sums ----
    float* smt = (float*)sm;  // [64 o][132 pad]
#pragma unroll
    for (int fm = 0; fm < 2; fm++) {
        const int sl = wm * 32 + fm * 16 + (lane >> 2);
#pragma unroll
        for (int fn = 0; fn < 4; fn++) {
            const int oc = wn * 32 + fn * 8 + (lane & 3) * 2;
            smt[oc * 132 + sl] = acc[fm][fn][0];
            smt[(oc + 1) * 132 + sl] = acc[fm][fn][1];
            smt[oc * 132 + sl + 8] = acc[fm][fn][2];
            smt[(oc + 1) * 132 + sl + 8] = acc[fm][fn][3];
        }
    }
    __syncthreads();
    const int b = m0 >> 9;
    const int sbase = m0 & 511;
    const int ol = tid >> 2, seg = tid & 3;
    float* dst = &g_uhat[((size_t)b * 512 + n0 + ol) * 512 + sbase + seg * 32];
    const float* srcT = &smt[ol * 132 + seg * 32];
    float csum = 0.f;
#pragma unroll
    for (int j = 0; j < 8; j++) {
        const float4 v = *(const float4*)&srcT[j * 4];
        csum += (v.x + v.y) + (v.z + v.w);
        *(float4*)&dst[j * 4] = v;
    }
    atomicAdd(&g_colsum[(size_t)b * 512 + n0 + ol], csum);
}

// ---------------- Routing: passes 1,2 (pass 0 fused into GEMM) ----------------
__global__ __launch_bounds__(512) void caps_routing(float* __restrict__ out) {
    __shared__ float outsm[O_DIM];
    __shared__ float bsm[NC][33];
    __shared__ float csm[32][17];
    const int bidx = blockIdx.x;
    const int lane = threadIdx.x & 31;
    const int w = threadIdx.x >> 5;
    const float* __restrict__ u =
        g_uhat + (size_t)bidx * O_DIM * S_DIM + (size_t)w * 32 * S_DIM + lane;

    {
        const float myv = g_colsum[(size_t)bidx * 512 + threadIdx.x] * (1.f / 16.f);
        float ss = myv * myv;
#pragma unroll
        for (int o = 16; o > 0; o >>= 1) ss += __shfl_xor_sync(0xffffffffu, ss, o);
        outsm[threadIdx.x] = myv / sqrtf(ss + 1e-7f);
    }

    float acc[32];
    for (int it = 1; it < 3; it++) {
        __syncthreads();
#pragma unroll
        for (int r2 = 0; r2 < 32; r2++) acc[r2] = 0.f;

        for (int chunk = 0; chunk < 16; chunk++) {
            const float* up = u + chunk * 32;
            float val[32];
#pragma unroll
            for (int r2 = 0; r2 < 32; r2++) val[r2] = up[(size_t)r2 * S_DIM];

            float bl = 0.f;
#pragma unroll
            for (int r2 = 0; r2 < 32; r2++) bl += outsm[w * 32 + r2] * val[r2];
            bsm[w][lane] = bl;
            __syncthreads();

            {
                const int sp = lane >> 4, n = lane & 15;
                const float bv = bsm[n][2 * w + sp];
                float mx = bv;
#pragma unroll
                for (int o = 8; o > 0; o >>= 1) mx = fmaxf(mx, __shfl_xor_sync(0xffffffffu, mx, o));
                const float e = __expf(bv - mx);
                float den = e;
#pragma unroll
                for (int o = 8; o > 0; o >>= 1) den += __shfl_xor_sync(0xffffffffu, den, o);
                csm[2 * w + sp][n] = e / den;
            }
            __syncthreads();

            const float cw = csm[lane][w];
#pragma unroll
            for (int r2 = 0; r2 < 32; r2++) acc[r2] += cw * val[r2];
        }

        float myv = 0.f;
#pragma unroll
        for (int r2 = 0; r2 < 32; r2++) {
            float t = acc[r2];
#pragma unroll
            for (int o = 16; o > 0; o >>= 1) t += __shfl_xor_sync(0xffffffffu, t, o);
            if (lane == r2) myv = t;
        }
        float ss = myv * myv;
#pragma unroll
        for (int o = 16; o > 0; o >>= 1) ss += __shfl_xor_sync(0xffffffffu, ss, o);
        const float res = myv / sqrtf(ss + 1e-7f);
        if (it == 2) out[(size_t)bidx * O_DIM + w * 32 + lane] = res;
        else outsm[w * 32 + lane] = res;
    }
}

extern "C" void kernel_launch(void* const* d_in, const int* in_sizes, int n_in,
                              void* d_out, int out_size) {
    const float* x = (const float*)d_in[0];
    const float* W = (const float*)d_in[1];
    float* out = (float*)d_out;

    split_x<<<32768, 256>>>(x);
    split_w<<<512, 256>>>(W);
    zero_colsum<<<256, 512>>>();
    cudaFuncSetAttribute(caps_gemm, cudaFuncAttributeMaxDynamicSharedMemorySize, SMEM_DYN);
    dim3 grid(O_DIM / 64, M_DIM / 128);  // (8, 1024)
    caps_gemm<<<grid, 256, SMEM_DYN>>>();
    caps_routing<<<B_DIM, 512>>>(out);
}

// round 8
// speedup vs baseline: 2.0471x; 1.1259x over previous
#include <cuda_runtime.h>
#include <cuda_fp16.h>
#include <cstdint>

#define NC 16
#define DC 32
#define S_DIM 512
#define D_DIM 256
#define O_DIM 512
#define B_DIM 256
#define M_DIM (B_DIM * S_DIM)  // 131072

// u_hat TRANSPOSED: [b][o][s]
__device__ float g_uhat[(size_t)B_DIM * O_DIM * S_DIM];
__device__ float g_colsum[(size_t)B_DIM * O_DIM];
// fp16 split of x: [m][0..255]=hi, [256..511]=lo ; W single fp16 [k][n]
__device__ __half g_xs[(size_t)M_DIM * 512];
__device__ __half g_ws[256 * 512];

// ---------------- PTX helpers ----------------
#define LDMX4(r, addr)                                                                   \
    asm volatile("ldmatrix.sync.aligned.m8n8.x4.shared.b16 {%0,%1,%2,%3}, [%4];"         \
                 : "=r"((r)[0]), "=r"((r)[1]), "=r"((r)[2]), "=r"((r)[3]) : "r"(addr))
#define LDMX4T(r, addr)                                                                  \
    asm volatile("ldmatrix.sync.aligned.m8n8.x4.trans.shared.b16 {%0,%1,%2,%3}, [%4];"   \
                 : "=r"((r)[0]), "=r"((r)[1]), "=r"((r)[2]), "=r"((r)[3]) : "r"(addr))
#define MMA_FP16(d, a, b0, b1)                                                           \
    asm volatile("mma.sync.aligned.m16n8k16.row.col.f32.f16.f16.f32 "                    \
                 "{%0,%1,%2,%3}, {%4,%5,%6,%7}, {%8,%9}, {%0,%1,%2,%3};"                 \
                 : "+f"((d)[0]), "+f"((d)[1]), "+f"((d)[2]), "+f"((d)[3])                \
                 : "r"((a)[0]), "r"((a)[1]), "r"((a)[2]), "r"((a)[3]), "r"(b0), "r"(b1))
#define CP16(dst, src)                                                                   \
    asm volatile("cp.async.cg.shared.global [%0], [%1], 16;" :: "r"(dst), "l"(src))
#define CPCOMMIT() asm volatile("cp.async.commit_group;")
#define CPWAIT(n)  asm volatile("cp.async.wait_group %0;" :: "n"(n))

__device__ __forceinline__ uint32_t smem_u32(const void* p) {
    uint32_t a;
    asm("{ .reg .u64 t; cvta.to.shared.u64 t, %1; cvt.u32.u64 %0, t; }" : "=r"(a) : "l"(p));
    return a;
}

// ---------------- split precompute ----------------
__global__ __launch_bounds__(256) void split_x(const float* __restrict__ x) {
    const size_t j = (size_t)blockIdx.x * 256 + threadIdx.x;
    const size_t m = j >> 6;
    const int c4 = (int)(j & 63) * 4;
    const float4 f = *(const float4*)&x[m * D_DIM + c4];
    const __half h0 = __float2half(f.x), h1 = __float2half(f.y);
    const __half h2 = __float2half(f.z), h3 = __float2half(f.w);
    const __half l0 = __float2half(f.x - __half2float(h0));
    const __half l1 = __float2half(f.y - __half2float(h1));
    const __half l2 = __float2half(f.z - __half2float(h2));
    const __half l3 = __float2half(f.w - __half2float(h3));
    __half2 H0(h0, h1), H1(h2, h3), L0(l0, l1), L1(l2, l3);
    *(uint2*)&g_xs[m * 512 + c4] = make_uint2(*(uint32_t*)&H0, *(uint32_t*)&H1);
    *(uint2*)&g_xs[m * 512 + 256 + c4] = make_uint2(*(uint32_t*)&L0, *(uint32_t*)&L1);
}

__global__ __launch_bounds__(256) void split_w(const float* __restrict__ W) {
    const int i = blockIdx.x * 256 + threadIdx.x;  // 131072 elems
    g_ws[i] = __float2half(W[i]);
}

__global__ __launch_bounds__(512) void zero_colsum() {
    g_colsum[(size_t)blockIdx.x * 512 + threadIdx.x] = 0.f;
}

// ---------------- GEMM: tile 128x64, BK=32, 256 threads, 2 stages, 3 CTAs/SM ----------------
#define ASTR 40
#define BSTR 72
#define OFF_AL 10240   // 128*40*2
#define OFF_B  20480
#define STAGE  25088   // + 32*72*2 = 4608
#define SMEM_DYN (2 * STAGE)  // 50176; also >= 64*132*4 transpose buffer

__global__ __launch_bounds__(256, 3) void caps_gemm() {
    extern __shared__ char sm[];
    const uint32_t smb = smem_u32(sm);
    const int tid = threadIdx.x;
    const int wid = tid >> 5, lane = tid & 31;
    const int wm = wid >> 1, wn = wid & 1;   // 4x2 warps, warp tile 32x32
    const int m0 = blockIdx.y * 128;
    const int n0 = blockIdx.x * 64;

    // cp.async source/dest
    const int arow = tid >> 1, ahalf = tid & 1;
    const int brow = tid >> 3, bg = tid & 7;
    const uint64_t srcAh = __cvta_generic_to_global(&g_xs[(size_t)(m0 + arow) * 512 + ahalf * 16]);
    const uint64_t srcAl = srcAh + 256 * 2;
    const uint64_t srcB  = __cvta_generic_to_global(&g_ws[(size_t)brow * 512 + n0 + bg * 8]);
    const uint32_t dstA = smb + (uint32_t)(arow * ASTR + ahalf * 16) * 2;
    const uint32_t dstB = smb + OFF_B + (uint32_t)(brow * BSTR + bg * 8) * 2;

    // ldmatrix per-lane offsets
    const int mat = lane >> 3, r = lane & 7;
    uint32_t a_off[2], b_off[2];
#pragma unroll
    for (int fm = 0; fm < 2; fm++)
        a_off[fm] = (uint32_t)(((wm * 32 + fm * 16 + (mat & 1) * 8 + r) * ASTR + (mat >> 1) * 8) * 2);
#pragma unroll
    for (int nf2 = 0; nf2 < 2; nf2++)
        b_off[nf2] = (uint32_t)((((mat & 1) * 8 + r) * BSTR + (mat >> 1) * 8 + wn * 32 + nf2 * 16) * 2);

    float acc[2][4][4];
#pragma unroll
    for (int i = 0; i < 2; i++)
#pragma unroll
        for (int j = 0; j < 4; j++)
#pragma unroll
            for (int k = 0; k < 4; k++) acc[i][j][k] = 0.f;

#define ISSUE(kc) do {                                                     \
        const uint32_t bb = ((kc) & 1) * STAGE;                            \
        const uint64_t ka = (uint64_t)(kc) * 64;                           \
        CP16(dstA + bb, srcAh + ka); CP16(dstA + bb + 16, srcAh + ka + 16);\
        CP16(dstA + bb + OFF_AL, srcAl + ka);                              \
        CP16(dstA + bb + OFF_AL + 16, srcAl + ka + 16);                    \
        CP16(dstB + bb, srcB + (uint64_t)(kc) * 32768);                    \
        CPCOMMIT();                                                        \
    } while (0)

    ISSUE(0);
    for (int kc = 0; kc < 8; kc++) {
        if (kc < 7) { ISSUE(kc + 1); CPWAIT(1); } else { CPWAIT(0); }
        __syncthreads();
        const uint32_t sb = smb + (kc & 1) * STAGE;
#pragma unroll
        for (int ks = 0; ks < 2; ks++) {
            uint32_t Ah[2][4], Al[2][4], Bf[2][4];
#pragma unroll
            for (int fm = 0; fm < 2; fm++) {
                LDMX4(Ah[fm], sb + a_off[fm] + ks * 32);
                LDMX4(Al[fm], sb + OFF_AL + a_off[fm] + ks * 32);
            }
#pragma unroll
            for (int nf2 = 0; nf2 < 2; nf2++)
                LDMX4T(Bf[nf2], sb + OFF_B + b_off[nf2] + ks * 16 * BSTR * 2);
            // variant-major: consecutive MMAs hit distinct accumulators
#pragma unroll
            for (int v = 0; v < 2; v++)
#pragma unroll
                for (int nf2 = 0; nf2 < 2; nf2++)
#pragma unroll
                    for (int fm = 0; fm < 2; fm++)
#pragma unroll
                        for (int h = 0; h < 2; h++) {
                            const uint32_t* Af = v ? Al[fm] : Ah[fm];
                            MMA_FP16(acc[fm][nf2 * 2 + h], Af, Bf[nf2][h * 2], Bf[nf2][h * 2 + 1]);
                        }
        }
        __syncthreads();
    }

    // ---- epilogue: transpose in smem, write u_t[b][o][s], fused column sums ----
    float* smt = (float*)sm;  // [64 o][132 pad]
#pragma unroll
    for (int fm = 0; fm < 2; fm++) {
        const int sl = wm * 32 + fm * 16 + (lane >> 2);
#pragma unroll
        for (int fn = 0; fn < 4; fn++) {
            const int oc = wn * 32 + fn * 8 + (lane & 3) * 2;
            smt[oc * 132 + sl] = acc[fm][fn][0];
            smt[(oc + 1) * 132 + sl] = acc[fm][fn][1];
            smt[oc * 132 + sl + 8] = acc[fm][fn][2];
            smt[(oc + 1) * 132 + sl + 8] = acc[fm][fn][3];
        }
    }
    __syncthreads();
    const int b = m0 >> 9;
    const int sbase = m0 & 511;
    const int ol = tid >> 2, seg = tid & 3;
    float* dst = &g_uhat[((size_t)b * 512 + n0 + ol) * 512 + sbase + seg * 32];
    const float* srcT = &smt[ol * 132 + seg * 32];
    float csum = 0.f;
#pragma unroll
    for (int j = 0; j < 8; j++) {
        const float4 v = *(const float4*)&srcT[j * 4];
        csum += (v.x + v.y) + (v.z + v.w);
        *(float4*)&dst[j * 4] = v;
    }
    atomicAdd(&g_colsum[(size_t)b * 512 + n0 + ol], csum);
}

// ---------------- Routing: passes 1,2 (pass 0 fused into GEMM) ----------------
__global__ __launch_bounds__(512) void caps_routing(float* __restrict__ out) {
    __shared__ float outsm[O_DIM];
    __shared__ float bsm[NC][33];
    __shared__ float csm[32][17];
    const int bidx = blockIdx.x;
    const int lane = threadIdx.x & 31;
    const int w = threadIdx.x >> 5;
    const float* __restrict__ u =
        g_uhat + (size_t)bidx * O_DIM * S_DIM + (size_t)w * 32 * S_DIM + lane;

    {
        const float myv = g_colsum[(size_t)bidx * 512 + threadIdx.x] * (1.f / 16.f);
        float ss = myv * myv;
#pragma unroll
        for (int o = 16; o > 0; o >>= 1) ss += __shfl_xor_sync(0xffffffffu, ss, o);
        outsm[threadIdx.x] = myv / sqrtf(ss + 1e-7f);
    }

    float acc[32];
    for (int it = 1; it < 3; it++) {
        __syncthreads();
#pragma unroll
        for (int r2 = 0; r2 < 32; r2++) acc[r2] = 0.f;

        for (int chunk = 0; chunk < 16; chunk++) {
            const float* up = u + chunk * 32;
            float val[32];
#pragma unroll
            for (int r2 = 0; r2 < 32; r2++) val[r2] = up[(size_t)r2 * S_DIM];

            float bl = 0.f;
#pragma unroll
            for (int r2 = 0; r2 < 32; r2++) bl += outsm[w * 32 + r2] * val[r2];
            bsm[w][lane] = bl;
            __syncthreads();

            {
                const int sp = lane >> 4, n = lane & 15;
                const float bv = bsm[n][2 * w + sp];
                float mx = bv;
#pragma unroll
                for (int o = 8; o > 0; o >>= 1) mx = fmaxf(mx, __shfl_xor_sync(0xffffffffu, mx, o));
                const float e = __expf(bv - mx);
                float den = e;
#pragma unroll
                for (int o = 8; o > 0; o >>= 1) den += __shfl_xor_sync(0xffffffffu, den, o);
                csm[2 * w + sp][n] = e / den;
            }
            __syncthreads();

            const float cw = csm[lane][w];
#pragma unroll
            for (int r2 = 0; r2 < 32; r2++) acc[r2] += cw * val[r2];
        }

        float myv = 0.f;
#pragma unroll
        for (int r2 = 0; r2 < 32; r2++) {
            float t = acc[r2];
#pragma unroll
            for (int o = 16; o > 0; o >>= 1) t += __shfl_xor_sync(0xffffffffu, t, o);
            if (lane == r2) myv = t;
        }
        float ss = myv * myv;
#pragma unroll
        for (int o = 16; o > 0; o >>= 1) ss += __shfl_xor_sync(0xffffffffu, ss, o);
        const float res = myv / sqrtf(ss + 1e-7f);
        if (it == 2) out[(size_t)bidx * O_DIM + w * 32 + lane] = res;
        else outsm[w * 32 + lane] = res;
    }
}

extern "C" void kernel_launch(void* const* d_in, const int* in_sizes, int n_in,
                              void* d_out, int out_size) {
    const float* x = (const float*)d_in[0];
    const float* W = (const float*)d_in[1];
    float* out = (float*)d_out;

    split_x<<<32768, 256>>>(x);
    split_w<<<512, 256>>>(W);
    zero_colsum<<<256, 512>>>();
    cudaFuncSetAttribute(caps_gemm, cudaFuncAttributeMaxDynamicSharedMemorySize, SMEM_DYN);
    dim3 grid(O_DIM / 64, M_DIM / 128);  // (8, 1024)
    caps_gemm<<<grid, 256, SMEM_DYN>>>();
    caps_routing<<<B_DIM, 512>>>(out);
}

// round 9
// speedup vs baseline: 2.1634x; 1.0568x over previous
#include <cuda_runtime.h>
#include <cuda_fp16.h>
#include <cstdint>

#define NC 16
#define DC 32
#define S_DIM 512
#define D_DIM 256
#define O_DIM 512
#define B_DIM 256
#define M_DIM (B_DIM * S_DIM)  // 131072

// u_hat TRANSPOSED: [b][o][s]
__device__ float g_uhat[(size_t)B_DIM * O_DIM * S_DIM];
__device__ float g_colsum[(size_t)B_DIM * O_DIM];
// fp16 split of x: [m][0..255]=hi, [256..511]=lo ; W single fp16 [k][n]
__device__ __half g_xs[(size_t)M_DIM * 512];
__device__ __half g_ws[256 * 512];

// ---------------- PTX helpers ----------------
#define LDMX4(r, addr)                                                                   \
    asm volatile("ldmatrix.sync.aligned.m8n8.x4.shared.b16 {%0,%1,%2,%3}, [%4];"         \
                 : "=r"((r)[0]), "=r"((r)[1]), "=r"((r)[2]), "=r"((r)[3]) : "r"(addr))
#define LDMX4T(r, addr)                                                                  \
    asm volatile("ldmatrix.sync.aligned.m8n8.x4.trans.shared.b16 {%0,%1,%2,%3}, [%4];"   \
                 : "=r"((r)[0]), "=r"((r)[1]), "=r"((r)[2]), "=r"((r)[3]) : "r"(addr))
#define MMA_FP16(d, a, b0, b1)                                                           \
    asm volatile("mma.sync.aligned.m16n8k16.row.col.f32.f16.f16.f32 "                    \
                 "{%0,%1,%2,%3}, {%4,%5,%6,%7}, {%8,%9}, {%0,%1,%2,%3};"                 \
                 : "+f"((d)[0]), "+f"((d)[1]), "+f"((d)[2]), "+f"((d)[3])                \
                 : "r"((a)[0]), "r"((a)[1]), "r"((a)[2]), "r"((a)[3]), "r"(b0), "r"(b1))
#define CP16(dst, src)                                                                   \
    asm volatile("cp.async.cg.shared.global [%0], [%1], 16;" :: "r"(dst), "l"(src))
#define CPCOMMIT() asm volatile("cp.async.commit_group;")
#define CPWAIT(n)  asm volatile("cp.async.wait_group %0;" :: "n"(n))

__device__ __forceinline__ uint32_t smem_u32(const void* p) {
    uint32_t a;
    asm("{ .reg .u64 t; cvta.to.shared.u64 t, %1; cvt.u32.u64 %0, t; }" : "=r"(a) : "l"(p));
    return a;
}

// ---------------- split precompute ----------------
__global__ __launch_bounds__(256) void split_x(const float* __restrict__ x) {
    const size_t j = (size_t)blockIdx.x * 256 + threadIdx.x;
    const size_t m = j >> 6;
    const int c4 = (int)(j & 63) * 4;
    const float4 f = *(const float4*)&x[m * D_DIM + c4];
    const __half h0 = __float2half(f.x), h1 = __float2half(f.y);
    const __half h2 = __float2half(f.z), h3 = __float2half(f.w);
    const __half l0 = __float2half(f.x - __half2float(h0));
    const __half l1 = __float2half(f.y - __half2float(h1));
    const __half l2 = __float2half(f.z - __half2float(h2));
    const __half l3 = __float2half(f.w - __half2float(h3));
    __half2 H0(h0, h1), H1(h2, h3), L0(l0, l1), L1(l2, l3);
    *(uint2*)&g_xs[m * 512 + c4] = make_uint2(*(uint32_t*)&H0, *(uint32_t*)&H1);
    *(uint2*)&g_xs[m * 512 + 256 + c4] = make_uint2(*(uint32_t*)&L0, *(uint32_t*)&L1);
}

__global__ __launch_bounds__(256) void split_w(const float* __restrict__ W) {
    const int i = blockIdx.x * 256 + threadIdx.x;
    g_ws[i] = __float2half(W[i]);
}

__global__ __launch_bounds__(512) void zero_colsum() {
    g_colsum[(size_t)blockIdx.x * 512 + threadIdx.x] = 0.f;
}

// ---------------- GEMM: tile 128x128, BK=32, 256 threads, warp tile 32x64 ----------------
#define ASTR 40
#define BSTR 136
#define OFF_AL 10240   // 128*40*2
#define OFF_B  20480
#define STAGE  29184   // + 32*136*2 = 8704
#define SMEM_DYN (2 * STAGE)  // 58368; also >= 64*132*4 = 33792 transpose buffer

__global__ __launch_bounds__(256, 2) void caps_gemm() {
    extern __shared__ char sm[];
    const uint32_t smb = smem_u32(sm);
    const int tid = threadIdx.x;
    const int wid = tid >> 5, lane = tid & 31;
    const int wm = wid >> 1, wn = wid & 1;   // 4m x 2n warps, warp tile 32x64
    const int m0 = blockIdx.y * 128;
    const int n0 = blockIdx.x * 128;

    // cp.async source/dest
    const int arow = tid >> 1, ahalf = tid & 1;     // A: 128 rows x 2 halves of 16
    const int brow = tid >> 4, bg = tid & 15;       // B: 16 rows x 16 groups of 8 (x2 passes)
    const uint64_t srcAh = __cvta_generic_to_global(&g_xs[(size_t)(m0 + arow) * 512 + ahalf * 16]);
    const uint64_t srcAl = srcAh + 256 * 2;
    const uint64_t srcB  = __cvta_generic_to_global(&g_ws[(size_t)brow * 512 + n0 + bg * 8]);
    const uint32_t dstA = smb + (uint32_t)(arow * ASTR + ahalf * 16) * 2;
    const uint32_t dstB = smb + OFF_B + (uint32_t)(brow * BSTR + bg * 8) * 2;

    // ldmatrix per-lane offsets
    const int mat = lane >> 3, r = lane & 7;
    uint32_t a_off[2], b_off[4];
#pragma unroll
    for (int fm = 0; fm < 2; fm++)
        a_off[fm] = (uint32_t)(((wm * 32 + fm * 16 + (mat & 1) * 8 + r) * ASTR + (mat >> 1) * 8) * 2);
#pragma unroll
    for (int nb = 0; nb < 4; nb++)
        b_off[nb] = (uint32_t)((((mat & 1) * 8 + r) * BSTR + (mat >> 1) * 8 + wn * 64 + nb * 16) * 2);

    float acc[2][8][4];
#pragma unroll
    for (int i = 0; i < 2; i++)
#pragma unroll
        for (int j = 0; j < 8; j++)
#pragma unroll
            for (int k = 0; k < 4; k++) acc[i][j][k] = 0.f;

#define ISSUE(kc) do {                                                     \
        const uint32_t bb = ((kc) & 1) * STAGE;                            \
        const uint64_t ka = (uint64_t)(kc) * 64;                           \
        CP16(dstA + bb, srcAh + ka); CP16(dstA + bb + 16, srcAh + ka + 16);\
        CP16(dstA + bb + OFF_AL, srcAl + ka);                              \
        CP16(dstA + bb + OFF_AL + 16, srcAl + ka + 16);                    \
        const uint64_t kb = (uint64_t)(kc) * 32768;                        \
        CP16(dstB + bb, srcB + kb);                                        \
        CP16(dstB + bb + 16 * BSTR * 2, srcB + kb + 16 * 512 * 2);         \
        CPCOMMIT();                                                        \
    } while (0)

    ISSUE(0);
    for (int kc = 0; kc < 8; kc++) {
        if (kc < 7) { ISSUE(kc + 1); CPWAIT(1); } else { CPWAIT(0); }
        __syncthreads();
        const uint32_t sb = smb + (kc & 1) * STAGE;
#pragma unroll
        for (int ks = 0; ks < 2; ks++) {
            uint32_t Ah[2][4], Al[2][4], Bf[4][4];
#pragma unroll
            for (int fm = 0; fm < 2; fm++) {
                LDMX4(Ah[fm], sb + a_off[fm] + ks * 32);
                LDMX4(Al[fm], sb + OFF_AL + a_off[fm] + ks * 32);
            }
#pragma unroll
            for (int nb = 0; nb < 4; nb++)
                LDMX4T(Bf[nb], sb + OFF_B + b_off[nb] + ks * 16 * BSTR * 2);
            // variant-major round-robin over 16 accumulators
#pragma unroll
            for (int v = 0; v < 2; v++)
#pragma unroll
                for (int nb = 0; nb < 4; nb++)
#pragma unroll
                    for (int fm = 0; fm < 2; fm++)
#pragma unroll
                        for (int h = 0; h < 2; h++) {
                            const uint32_t* Af = v ? Al[fm] : Ah[fm];
                            MMA_FP16(acc[fm][nb * 2 + h], Af, Bf[nb][h * 2], Bf[nb][h * 2 + 1]);
                        }
        }
        __syncthreads();
    }

    // ---- epilogue: two o-half passes; transpose + write u_t[b][o][s] + colsums ----
    float* smt = (float*)sm;  // [64 o][132 s-pad]
    const int b = m0 >> 9;
    const int sbase = m0 & 511;
    const int ol = tid >> 2, seg = tid & 3;
#pragma unroll
    for (int p = 0; p < 2; p++) {
        __syncthreads();
        if (wn == p) {
#pragma unroll
            for (int fm = 0; fm < 2; fm++) {
                const int sl = wm * 32 + fm * 16 + (lane >> 2);
#pragma unroll
                for (int fn = 0; fn < 8; fn++) {
                    const int oc = fn * 8 + (lane & 3) * 2;
                    smt[oc * 132 + sl] = acc[fm][fn][0];
                    smt[(oc + 1) * 132 + sl] = acc[fm][fn][1];
                    smt[oc * 132 + sl + 8] = acc[fm][fn][2];
                    smt[(oc + 1) * 132 + sl + 8] = acc[fm][fn][3];
                }
            }
        }
        __syncthreads();
        float* dst = &g_uhat[((size_t)b * 512 + n0 + p * 64 + ol) * 512 + sbase + seg * 32];
        const float* srcT = &smt[ol * 132 + seg * 32];
        float csum = 0.f;
#pragma unroll
        for (int j = 0; j < 8; j++) {
            const float4 v = *(const float4*)&srcT[j * 4];
            csum += (v.x + v.y) + (v.z + v.w);
            *(float4*)&dst[j * 4] = v;
        }
        atomicAdd(&g_colsum[(size_t)b * 512 + n0 + p * 64 + ol], csum);
    }
}

// ---------------- Routing: passes 1,2 (pass 0 fused into GEMM) ----------------
__global__ __launch_bounds__(512) void caps_routing(float* __restrict__ out) {
    __shared__ float outsm[O_DIM];
    __shared__ float bsm[NC][33];
    __shared__ float csm[32][17];
    const int bidx = blockIdx.x;
    const int lane = threadIdx.x & 31;
    const int w = threadIdx.x >> 5;
    const float* __restrict__ u =
        g_uhat + (size_t)bidx * O_DIM * S_DIM + (size_t)w * 32 * S_DIM + lane;

    {
        const float myv = g_colsum[(size_t)bidx * 512 + threadIdx.x] * (1.f / 16.f);
        float ss = myv * myv;
#pragma unroll
        for (int o = 16; o > 0; o >>= 1) ss += __shfl_xor_sync(0xffffffffu, ss, o);
        outsm[threadIdx.x] = myv / sqrtf(ss + 1e-7f);
    }

    float acc[32];
    for (int it = 1; it < 3; it++) {
        __syncthreads();
#pragma unroll
        for (int r2 = 0; r2 < 32; r2++) acc[r2] = 0.f;

        for (int chunk = 0; chunk < 16; chunk++) {
            const float* up = u + chunk * 32;
            float val[32];
#pragma unroll
            for (int r2 = 0; r2 < 32; r2++) val[r2] = up[(size_t)r2 * S_DIM];

            float bl = 0.f;
#pragma unroll
            for (int r2 = 0; r2 < 32; r2++) bl += outsm[w * 32 + r2] * val[r2];
            bsm[w][lane] = bl;
            __syncthreads();

            {
                const int sp = lane >> 4, n = lane & 15;
                const float bv = bsm[n][2 * w + sp];
                float mx = bv;
#pragma unroll
                for (int o = 8; o > 0; o >>= 1) mx = fmaxf(mx, __shfl_xor_sync(0xffffffffu, mx, o));
                const float e = __expf(bv - mx);
                float den = e;
#pragma unroll
                for (int o = 8; o > 0; o >>= 1) den += __shfl_xor_sync(0xffffffffu, den, o);
                csm[2 * w + sp][n] = e / den;
            }
            __syncthreads();

            const float cw = csm[lane][w];
#pragma unroll
            for (int r2 = 0; r2 < 32; r2++) acc[r2] += cw * val[r2];
        }

        float myv = 0.f;
#pragma unroll
        for (int r2 = 0; r2 < 32; r2++) {
            float t = acc[r2];
#pragma unroll
            for (int o = 16; o > 0; o >>= 1) t += __shfl_xor_sync(0xffffffffu, t, o);
            if (lane == r2) myv = t;
        }
        float ss = myv * myv;
#pragma unroll
        for (int o = 16; o > 0; o >>= 1) ss += __shfl_xor_sync(0xffffffffu, ss, o);
        const float res = myv / sqrtf(ss + 1e-7f);
        if (it == 2) out[(size_t)bidx * O_DIM + w * 32 + lane] = res;
        else outsm[w * 32 + lane] = res;
    }
}

extern "C" void kernel_launch(void* const* d_in, const int* in_sizes, int n_in,
                              void* d_out, int out_size) {
    const float* x = (const float*)d_in[0];
    const float* W = (const float*)d_in[1];
    float* out = (float*)d_out;

    split_x<<<32768, 256>>>(x);
    split_w<<<512, 256>>>(W);
    zero_colsum<<<256, 512>>>();
    cudaFuncSetAttribute(caps_gemm, cudaFuncAttributeMaxDynamicSharedMemorySize, SMEM_DYN);
    dim3 grid(O_DIM / 128, M_DIM / 128);  // (4, 1024)
    caps_gemm<<<grid, 256, SMEM_DYN>>>();
    caps_routing<<<B_DIM, 512>>>(out);
}

// round 10
// speedup vs baseline: 2.5218x; 1.1657x over previous
#include <cuda_runtime.h>
#include <cuda_fp16.h>
#include <cstdint>

#define NC 16
#define DC 32
#define S_DIM 512
#define D_DIM 256
#define O_DIM 512
#define B_DIM 256
#define M_DIM (B_DIM * S_DIM)  // 131072

// u_hat TRANSPOSED, fp16: [b][o][s]
__device__ __half g_uhat[(size_t)B_DIM * O_DIM * S_DIM];
__device__ float g_colsum[(size_t)B_DIM * O_DIM];
// fp16 split of x: [m][0..255]=hi, [256..511]=lo ; W single fp16 [k][n]
__device__ __half g_xs[(size_t)M_DIM * 512];
__device__ __half g_ws[256 * 512];

// ---------------- PTX helpers ----------------
#define LDMX4(r, addr)                                                                   \
    asm volatile("ldmatrix.sync.aligned.m8n8.x4.shared.b16 {%0,%1,%2,%3}, [%4];"         \
                 : "=r"((r)[0]), "=r"((r)[1]), "=r"((r)[2]), "=r"((r)[3]) : "r"(addr))
#define LDMX4T(r, addr)                                                                  \
    asm volatile("ldmatrix.sync.aligned.m8n8.x4.trans.shared.b16 {%0,%1,%2,%3}, [%4];"   \
                 : "=r"((r)[0]), "=r"((r)[1]), "=r"((r)[2]), "=r"((r)[3]) : "r"(addr))
#define MMA_FP16(d, a, b0, b1)                                                           \
    asm volatile("mma.sync.aligned.m16n8k16.row.col.f32.f16.f16.f32 "                    \
                 "{%0,%1,%2,%3}, {%4,%5,%6,%7}, {%8,%9}, {%0,%1,%2,%3};"                 \
                 : "+f"((d)[0]), "+f"((d)[1]), "+f"((d)[2]), "+f"((d)[3])                \
                 : "r"((a)[0]), "r"((a)[1]), "r"((a)[2]), "r"((a)[3]), "r"(b0), "r"(b1))
#define CP16(dst, src)                                                                   \
    asm volatile("cp.async.cg.shared.global [%0], [%1], 16;" :: "r"(dst), "l"(src))
#define CPCOMMIT() asm volatile("cp.async.commit_group;")
#define CPWAIT(n)  asm volatile("cp.async.wait_group %0;" :: "n"(n))

__device__ __forceinline__ uint32_t smem_u32(const void* p) {
    uint32_t a;
    asm("{ .reg .u64 t; cvta.to.shared.u64 t, %1; cvt.u32.u64 %0, t; }" : "=r"(a) : "l"(p));
    return a;
}

// ---------------- split precompute ----------------
__global__ __launch_bounds__(256) void split_x(const float* __restrict__ x) {
    const size_t j = (size_t)blockIdx.x * 256 + threadIdx.x;
    const size_t m = j >> 6;
    const int c4 = (int)(j & 63) * 4;
    const float4 f = *(const float4*)&x[m * D_DIM + c4];
    const __half h0 = __float2half(f.x), h1 = __float2half(f.y);
    const __half h2 = __float2half(f.z), h3 = __float2half(f.w);
    const __half l0 = __float2half(f.x - __half2float(h0));
    const __half l1 = __float2half(f.y - __half2float(h1));
    const __half l2 = __float2half(f.z - __half2float(h2));
    const __half l3 = __float2half(f.w - __half2float(h3));
    __half2 H0(h0, h1), H1(h2, h3), L0(l0, l1), L1(l2, l3);
    *(uint2*)&g_xs[m * 512 + c4] = make_uint2(*(uint32_t*)&H0, *(uint32_t*)&H1);
    *(uint2*)&g_xs[m * 512 + 256 + c4] = make_uint2(*(uint32_t*)&L0, *(uint32_t*)&L1);
}

__global__ __launch_bounds__(256) void split_w(const float* __restrict__ W) {
    const int i = blockIdx.x * 256 + threadIdx.x;
    g_ws[i] = __float2half(W[i]);
}

__global__ __launch_bounds__(512) void zero_colsum() {
    g_colsum[(size_t)blockIdx.x * 512 + threadIdx.x] = 0.f;
}

// ---------------- GEMM: tile 128x128, BK=32, 256 threads, warp tile 32x64 ----------------
#define ASTR 40
#define BSTR 136
#define OFF_AL 10240   // 128*40*2
#define OFF_B  20480
#define STAGE  29184   // + 32*136*2 = 8704
#define SMEM_DYN (2 * STAGE)  // 58368; also >= 64*132*4 = 33792 transpose buffer

__global__ __launch_bounds__(256, 2) void caps_gemm() {
    extern __shared__ char sm[];
    const uint32_t smb = smem_u32(sm);
    const int tid = threadIdx.x;
    const int wid = tid >> 5, lane = tid & 31;
    const int wm = wid >> 1, wn = wid & 1;   // 4m x 2n warps, warp tile 32x64
    const int m0 = blockIdx.y * 128;
    const int n0 = blockIdx.x * 128;

    // cp.async source/dest
    const int arow = tid >> 1, ahalf = tid & 1;
    const int brow = tid >> 4, bg = tid & 15;
    const uint64_t srcAh = __cvta_generic_to_global(&g_xs[(size_t)(m0 + arow) * 512 + ahalf * 16]);
    const uint64_t srcAl = srcAh + 256 * 2;
    const uint64_t srcB  = __cvta_generic_to_global(&g_ws[(size_t)brow * 512 + n0 + bg * 8]);
    const uint32_t dstA = smb + (uint32_t)(arow * ASTR + ahalf * 16) * 2;
    const uint32_t dstB = smb + OFF_B + (uint32_t)(brow * BSTR + bg * 8) * 2;

    // ldmatrix per-lane offsets
    const int mat = lane >> 3, r = lane & 7;
    uint32_t a_off[2], b_off[4];
#pragma unroll
    for (int fm = 0; fm < 2; fm++)
        a_off[fm] = (uint32_t)(((wm * 32 + fm * 16 + (mat & 1) * 8 + r) * ASTR + (mat >> 1) * 8) * 2);
#pragma unroll
    for (int nb = 0; nb < 4; nb++)
        b_off[nb] = (uint32_t)((((mat & 1) * 8 + r) * BSTR + (mat >> 1) * 8 + wn * 64 + nb * 16) * 2);

    float acc[2][8][4];
#pragma unroll
    for (int i = 0; i < 2; i++)
#pragma unroll
        for (int j = 0; j < 8; j++)
#pragma unroll
            for (int k = 0; k < 4; k++) acc[i][j][k] = 0.f;

#define ISSUE(kc) do {                                                     \
        const uint32_t bb = ((kc) & 1) * STAGE;                            \
        const uint64_t ka = (uint64_t)(kc) * 64;                           \
        CP16(dstA + bb, srcAh + ka); CP16(dstA + bb + 16, srcAh + ka + 16);\
        CP16(dstA + bb + OFF_AL, srcAl + ka);                              \
        CP16(dstA + bb + OFF_AL + 16, srcAl + ka + 16);                    \
        const uint64_t kb = (uint64_t)(kc) * 32768;                        \
        CP16(dstB + bb, srcB + kb);                                        \
        CP16(dstB + bb + 16 * BSTR * 2, srcB + kb + 16 * 512 * 2);         \
        CPCOMMIT();                                                        \
    } while (0)

    ISSUE(0);
    for (int kc = 0; kc < 8; kc++) {
        if (kc < 7) { ISSUE(kc + 1); CPWAIT(1); } else { CPWAIT(0); }
        __syncthreads();
        const uint32_t sb = smb + (kc & 1) * STAGE;
#pragma unroll
        for (int ks = 0; ks < 2; ks++) {
            uint32_t Ah[2][4], Al[2][4], Bf[4][4];
#pragma unroll
            for (int fm = 0; fm < 2; fm++) {
                LDMX4(Ah[fm], sb + a_off[fm] + ks * 32);
                LDMX4(Al[fm], sb + OFF_AL + a_off[fm] + ks * 32);
            }
#pragma unroll
            for (int nb = 0; nb < 4; nb++)
                LDMX4T(Bf[nb], sb + OFF_B + b_off[nb] + ks * 16 * BSTR * 2);
#pragma unroll
            for (int v = 0; v < 2; v++)
#pragma unroll
                for (int nb = 0; nb < 4; nb++)
#pragma unroll
                    for (int fm = 0; fm < 2; fm++)
#pragma unroll
                        for (int h = 0; h < 2; h++) {
                            const uint32_t* Af = v ? Al[fm] : Ah[fm];
                            MMA_FP16(acc[fm][nb * 2 + h], Af, Bf[nb][h * 2], Bf[nb][h * 2 + 1]);
                        }
        }
        __syncthreads();
    }

    // ---- epilogue: two o-half passes; transpose + fp16 write + colsums ----
    float* smt = (float*)sm;  // [64 o][132 s-pad]
    const int b = m0 >> 9;
    const int sbase = m0 & 511;
    const int ol = tid >> 2, seg = tid & 3;
#pragma unroll
    for (int p = 0; p < 2; p++) {
        __syncthreads();
        if (wn == p) {
#pragma unroll
            for (int fm = 0; fm < 2; fm++) {
                const int sl = wm * 32 + fm * 16 + (lane >> 2);
#pragma unroll
                for (int fn = 0; fn < 8; fn++) {
                    const int oc = fn * 8 + (lane & 3) * 2;
                    smt[oc * 132 + sl] = acc[fm][fn][0];
                    smt[(oc + 1) * 132 + sl] = acc[fm][fn][1];
                    smt[oc * 132 + sl + 8] = acc[fm][fn][2];
                    smt[(oc + 1) * 132 + sl + 8] = acc[fm][fn][3];
                }
            }
        }
        __syncthreads();
        __half* dst = &g_uhat[((size_t)b * 512 + n0 + p * 64 + ol) * 512 + sbase + seg * 32];
        const float* srcT = &smt[ol * 132 + seg * 32];
        float csum = 0.f;
#pragma unroll
        for (int j = 0; j < 4; j++) {
            const float4 v0 = *(const float4*)&srcT[j * 8];
            const float4 v1 = *(const float4*)&srcT[j * 8 + 4];
            csum += (v0.x + v0.y) + (v0.z + v0.w) + (v1.x + v1.y) + (v1.z + v1.w);
            __half2 p0 = __floats2half2_rn(v0.x, v0.y);
            __half2 p1 = __floats2half2_rn(v0.z, v0.w);
            __half2 p2 = __floats2half2_rn(v1.x, v1.y);
            __half2 p3 = __floats2half2_rn(v1.z, v1.w);
            uint4 o;
            o.x = *(uint32_t*)&p0; o.y = *(uint32_t*)&p1;
            o.z = *(uint32_t*)&p2; o.w = *(uint32_t*)&p3;
            *(uint4*)&dst[j * 8] = o;
        }
        atomicAdd(&g_colsum[(size_t)b * 512 + n0 + p * 64 + ol], csum);
    }
}

// ---------------- Routing: passes 1,2 on fp16 u_hat ----------------
__global__ __launch_bounds__(512) void caps_routing(float* __restrict__ out) {
    __shared__ float outsm[O_DIM];
    __shared__ float bsm[NC][33];
    __shared__ float csm[32][17];
    const int bidx = blockIdx.x;
    const int lane = threadIdx.x & 31;
    const int w = threadIdx.x >> 5;
    const __half* __restrict__ u =
        g_uhat + (size_t)bidx * O_DIM * S_DIM + (size_t)w * 32 * S_DIM + lane;

    {
        const float myv = g_colsum[(size_t)bidx * 512 + threadIdx.x] * (1.f / 16.f);
        float ss = myv * myv;
#pragma unroll
        for (int o = 16; o > 0; o >>= 1) ss += __shfl_xor_sync(0xffffffffu, ss, o);
        outsm[threadIdx.x] = myv / sqrtf(ss + 1e-7f);
    }

    float acc[32];
    for (int it = 1; it < 3; it++) {
        __syncthreads();
#pragma unroll
        for (int r2 = 0; r2 < 32; r2++) acc[r2] = 0.f;

        for (int chunk = 0; chunk < 16; chunk++) {
            const __half* up = u + chunk * 32;
            float val[32];
#pragma unroll
            for (int r2 = 0; r2 < 32; r2++) val[r2] = __half2float(up[(size_t)r2 * S_DIM]);

            float bl = 0.f;
#pragma unroll
            for (int r2 = 0; r2 < 32; r2++) bl += outsm[w * 32 + r2] * val[r2];
            bsm[w][lane] = bl;
            __syncthreads();

            {
                const int sp = lane >> 4, n = lane & 15;
                const float bv = bsm[n][2 * w + sp];
                float mx = bv;
#pragma unroll
                for (int o = 8; o > 0; o >>= 1) mx = fmaxf(mx, __shfl_xor_sync(0xffffffffu, mx, o));
                const float e = __expf(bv - mx);
                float den = e;
#pragma unroll
                for (int o = 8; o > 0; o >>= 1) den += __shfl_xor_sync(0xffffffffu, den, o);
                csm[2 * w + sp][n] = e / den;
            }
            __syncthreads();

            const float cw = csm[lane][w];
#pragma unroll
            for (int r2 = 0; r2 < 32; r2++) acc[r2] += cw * val[r2];
        }

        float myv = 0.f;
#pragma unroll
        for (int r2 = 0; r2 < 32; r2++) {
            float t = acc[r2];
#pragma unroll
            for (int o = 16; o > 0; o >>= 1) t += __shfl_xor_sync(0xffffffffu, t, o);
            if (lane == r2) myv = t;
        }
        float ss = myv * myv;
#pragma unroll
        for (int o = 16; o > 0; o >>= 1) ss += __shfl_xor_sync(0xffffffffu, ss, o);
        const float res = myv / sqrtf(ss + 1e-7f);
        if (it == 2) out[(size_t)bidx * O_DIM + w * 32 + lane] = res;
        else outsm[w * 32 + lane] = res;
    }
}

extern "C" void kernel_launch(void* const* d_in, const int* in_sizes, int n_in,
                              void* d_out, int out_size) {
    const float* x = (const float*)d_in[0];
    const float* W = (const float*)d_in[1];
    float* out = (float*)d_out;

    split_x<<<32768, 256>>>(x);
    split_w<<<512, 256>>>(W);
    zero_colsum<<<256, 512>>>();
    cudaFuncSetAttribute(caps_gemm, cudaFuncAttributeMaxDynamicSharedMemorySize, SMEM_DYN);
    dim3 grid(O_DIM / 128, M_DIM / 128);  // (4, 1024)
    caps_gemm<<<grid, 256, SMEM_DYN>>>();
    caps_routing<<<B_DIM, 512>>>(out);
}

// round 11
// speedup vs baseline: 3.2844x; 1.3024x over previous
#include <cuda_runtime.h>
#include <cuda_fp16.h>
#include <cstdint>

#define NC 16
#define DC 32
#define S_DIM 512
#define D_DIM 256
#define O_DIM 512
#define B_DIM 256
#define M_DIM (B_DIM * S_DIM)  // 131072

// u_hat TRANSPOSED, fp16: [b][o][s]
__device__ __half g_uhat[(size_t)B_DIM * O_DIM * S_DIM];
__device__ float g_colsum[(size_t)B_DIM * O_DIM];
// single fp16 conversions
__device__ __half g_xs[(size_t)M_DIM * 256];
__device__ __half g_ws[256 * 512];

// ---------------- PTX helpers ----------------
#define LDMX4(r, addr)                                                                   \
    asm volatile("ldmatrix.sync.aligned.m8n8.x4.shared.b16 {%0,%1,%2,%3}, [%4];"         \
                 : "=r"((r)[0]), "=r"((r)[1]), "=r"((r)[2]), "=r"((r)[3]) : "r"(addr))
#define LDMX4T(r, addr)                                                                  \
    asm volatile("ldmatrix.sync.aligned.m8n8.x4.trans.shared.b16 {%0,%1,%2,%3}, [%4];"   \
                 : "=r"((r)[0]), "=r"((r)[1]), "=r"((r)[2]), "=r"((r)[3]) : "r"(addr))
#define MMA_FP16(d, a, b0, b1)                                                           \
    asm volatile("mma.sync.aligned.m16n8k16.row.col.f32.f16.f16.f32 "                    \
                 "{%0,%1,%2,%3}, {%4,%5,%6,%7}, {%8,%9}, {%0,%1,%2,%3};"                 \
                 : "+f"((d)[0]), "+f"((d)[1]), "+f"((d)[2]), "+f"((d)[3])                \
                 : "r"((a)[0]), "r"((a)[1]), "r"((a)[2]), "r"((a)[3]), "r"(b0), "r"(b1))
#define CP16(dst, src)                                                                   \
    asm volatile("cp.async.cg.shared.global [%0], [%1], 16;" :: "r"(dst), "l"(src))
#define CPCOMMIT() asm volatile("cp.async.commit_group;")
#define CPWAIT(n)  asm volatile("cp.async.wait_group %0;" :: "n"(n))

__device__ __forceinline__ uint32_t smem_u32(const void* p) {
    uint32_t a;
    asm("{ .reg .u64 t; cvta.to.shared.u64 t, %1; cvt.u32.u64 %0, t; }" : "=r"(a) : "l"(p));
    return a;
}

// ---------------- convert precompute ----------------
__global__ __launch_bounds__(256) void split_x(const float* __restrict__ x) {
    const size_t j = (size_t)blockIdx.x * 256 + threadIdx.x;  // one float4 each
    const float4 f = *(const float4*)&x[j * 4];
    __half2 H0 = __floats2half2_rn(f.x, f.y);
    __half2 H1 = __floats2half2_rn(f.z, f.w);
    *(uint2*)&g_xs[j * 4] = make_uint2(*(uint32_t*)&H0, *(uint32_t*)&H1);
}

__global__ __launch_bounds__(256) void split_w(const float* __restrict__ W) {
    const int i = blockIdx.x * 256 + threadIdx.x;
    g_ws[i] = __float2half(W[i]);
}

__global__ __launch_bounds__(512) void zero_colsum() {
    g_colsum[(size_t)blockIdx.x * 512 + threadIdx.x] = 0.f;
}

// ---------------- GEMM: tile 128x128, BK=32, 256 threads, warp tile 32x64 ----------------
#define ASTR 40
#define BSTR 136
#define OFF_B  10240   // 128*40*2
#define STAGE  18944   // + 32*136*2 = 8704
#define SMEM_DYN (2 * STAGE)  // 37888; >= 64*132*4 = 33792 transpose buffer

__global__ __launch_bounds__(256, 2) void caps_gemm() {
    extern __shared__ char sm[];
    const uint32_t smb = smem_u32(sm);
    const int tid = threadIdx.x;
    const int wid = tid >> 5, lane = tid & 31;
    const int wm = wid >> 1, wn = wid & 1;   // 4m x 2n warps, warp tile 32x64
    const int m0 = blockIdx.y * 128;
    const int n0 = blockIdx.x * 128;

    // cp.async source/dest
    const int arow = tid >> 1, ahalf = tid & 1;   // A: 128 rows x 2 halves of 16 fp16
    const int brow = tid >> 4, bg = tid & 15;     // B: 16 rows x 16 groups of 8 (x2)
    const uint64_t srcA = __cvta_generic_to_global(&g_xs[(size_t)(m0 + arow) * 256 + ahalf * 16]);
    const uint64_t srcB = __cvta_generic_to_global(&g_ws[(size_t)brow * 512 + n0 + bg * 8]);
    const uint32_t dstA = smb + (uint32_t)(arow * ASTR + ahalf * 16) * 2;
    const uint32_t dstB = smb + OFF_B + (uint32_t)(brow * BSTR + bg * 8) * 2;

    // ldmatrix per-lane offsets
    const int mat = lane >> 3, r = lane & 7;
    uint32_t a_off[2], b_off[4];
#pragma unroll
    for (int fm = 0; fm < 2; fm++)
        a_off[fm] = (uint32_t)(((wm * 32 + fm * 16 + (mat & 1) * 8 + r) * ASTR + (mat >> 1) * 8) * 2);
#pragma unroll
    for (int nb = 0; nb < 4; nb++)
        b_off[nb] = (uint32_t)((((mat & 1) * 8 + r) * BSTR + (mat >> 1) * 8 + wn * 64 + nb * 16) * 2);

    float acc[2][8][4];
#pragma unroll
    for (int i = 0; i < 2; i++)
#pragma unroll
        for (int j = 0; j < 8; j++)
#pragma unroll
            for (int k = 0; k < 4; k++) acc[i][j][k] = 0.f;

#define ISSUE(kc) do {                                                     \
        const uint32_t bb = ((kc) & 1) * STAGE;                            \
        const uint64_t ka = (uint64_t)(kc) * 64;                           \
        CP16(dstA + bb, srcA + ka); CP16(dstA + bb + 16, srcA + ka + 16);  \
        const uint64_t kb = (uint64_t)(kc) * 32768;                        \
        CP16(dstB + bb, srcB + kb);                                        \
        CP16(dstB + bb + 16 * BSTR * 2, srcB + kb + 16 * 512 * 2);         \
        CPCOMMIT();                                                        \
    } while (0)

    ISSUE(0);
    for (int kc = 0; kc < 8; kc++) {
        if (kc < 7) { ISSUE(kc + 1); CPWAIT(1); } else { CPWAIT(0); }
        __syncthreads();
        const uint32_t sb = smb + (kc & 1) * STAGE;
#pragma unroll
        for (int ks = 0; ks < 2; ks++) {
            uint32_t Af[2][4], Bf[4][4];
#pragma unroll
            for (int fm = 0; fm < 2; fm++)
                LDMX4(Af[fm], sb + a_off[fm] + ks * 32);
#pragma unroll
            for (int nb = 0; nb < 4; nb++)
                LDMX4T(Bf[nb], sb + OFF_B + b_off[nb] + ks * 16 * BSTR * 2);
#pragma unroll
            for (int nb = 0; nb < 4; nb++)
#pragma unroll
                for (int fm = 0; fm < 2; fm++)
#pragma unroll
                    for (int h = 0; h < 2; h++)
                        MMA_FP16(acc[fm][nb * 2 + h], Af[fm], Bf[nb][h * 2], Bf[nb][h * 2 + 1]);
        }
        __syncthreads();
    }

    // ---- epilogue: two o-half passes; transpose + fp16 write + colsums ----
    float* smt = (float*)sm;  // [64 o][132 s-pad]
    const int b = m0 >> 9;
    const int sbase = m0 & 511;
    const int ol = tid >> 2, seg = tid & 3;
#pragma unroll
    for (int p = 0; p < 2; p++) {
        __syncthreads();
        if (wn == p) {
#pragma unroll
            for (int fm = 0; fm < 2; fm++) {
                const int sl = wm * 32 + fm * 16 + (lane >> 2);
#pragma unroll
                for (int fn = 0; fn < 8; fn++) {
                    const int oc = fn * 8 + (lane & 3) * 2;
                    smt[oc * 132 + sl] = acc[fm][fn][0];
                    smt[(oc + 1) * 132 + sl] = acc[fm][fn][1];
                    smt[oc * 132 + sl + 8] = acc[fm][fn][2];
                    smt[(oc + 1) * 132 + sl + 8] = acc[fm][fn][3];
                }
            }
        }
        __syncthreads();
        __half* dst = &g_uhat[((size_t)b * 512 + n0 + p * 64 + ol) * 512 + sbase + seg * 32];
        const float* srcT = &smt[ol * 132 + seg * 32];
        float csum = 0.f;
#pragma unroll
        for (int j = 0; j < 4; j++) {
            const float4 v0 = *(const float4*)&srcT[j * 8];
            const float4 v1 = *(const float4*)&srcT[j * 8 + 4];
            csum += (v0.x + v0.y) + (v0.z + v0.w) + (v1.x + v1.y) + (v1.z + v1.w);
            __half2 p0 = __floats2half2_rn(v0.x, v0.y);
            __half2 p1 = __floats2half2_rn(v0.z, v0.w);
            __half2 p2 = __floats2half2_rn(v1.x, v1.y);
            __half2 p3 = __floats2half2_rn(v1.z, v1.w);
            uint4 o;
            o.x = *(uint32_t*)&p0; o.y = *(uint32_t*)&p1;
            o.z = *(uint32_t*)&p2; o.w = *(uint32_t*)&p3;
            *(uint4*)&dst[j * 8] = o;
        }
        atomicAdd(&g_colsum[(size_t)b * 512 + n0 + p * 64 + ol], csum);
    }
}

// ---------------- Routing: passes 1,2 on fp16 u_hat ----------------
__global__ __launch_bounds__(512) void caps_routing(float* __restrict__ out) {
    __shared__ float outsm[O_DIM];
    __shared__ float bsm[NC][33];
    __shared__ float csm[32][17];
    const int bidx = blockIdx.x;
    const int lane = threadIdx.x & 31;
    const int w = threadIdx.x >> 5;
    const __half* __restrict__ u =
        g_uhat + (size_t)bidx * O_DIM * S_DIM + (size_t)w * 32 * S_DIM + lane;

    {
        const float myv = g_colsum[(size_t)bidx * 512 + threadIdx.x] * (1.f / 16.f);
        float ss = myv * myv;
#pragma unroll
        for (int o = 16; o > 0; o >>= 1) ss += __shfl_xor_sync(0xffffffffu, ss, o);
        outsm[threadIdx.x] = myv / sqrtf(ss + 1e-7f);
    }

    float acc[32];
    for (int it = 1; it < 3; it++) {
        __syncthreads();
#pragma unroll
        for (int r2 = 0; r2 < 32; r2++) acc[r2] = 0.f;

        for (int chunk = 0; chunk < 16; chunk++) {
            const __half* up = u + chunk * 32;
            float val[32];
#pragma unroll
            for (int r2 = 0; r2 < 32; r2++) val[r2] = __half2float(up[(size_t)r2 * S_DIM]);

            float bl = 0.f;
#pragma unroll
            for (int r2 = 0; r2 < 32; r2++) bl += outsm[w * 32 + r2] * val[r2];
            bsm[w][lane] = bl;
            __syncthreads();

            {
                const int sp = lane >> 4, n = lane & 15;
                const float bv = bsm[n][2 * w + sp];
                float mx = bv;
#pragma unroll
                for (int o = 8; o > 0; o >>= 1) mx = fmaxf(mx, __shfl_xor_sync(0xffffffffu, mx, o));
                const float e = __expf(bv - mx);
                float den = e;
#pragma unroll
                for (int o = 8; o > 0; o >>= 1) den += __shfl_xor_sync(0xffffffffu, den, o);
                csm[2 * w + sp][n] = e / den;
            }
            __syncthreads();

            const float cw = csm[lane][w];
#pragma unroll
            for (int r2 = 0; r2 < 32; r2++) acc[r2] += cw * val[r2];
        }

        float myv = 0.f;
#pragma unroll
        for (int r2 = 0; r2 < 32; r2++) {
            float t = acc[r2];
#pragma unroll
            for (int o = 16; o > 0; o >>= 1) t += __shfl_xor_sync(0xffffffffu, t, o);
            if (lane == r2) myv = t;
        }
        float ss = myv * myv;
#pragma unroll
        for (int o = 16; o > 0; o >>= 1) ss += __shfl_xor_sync(0xffffffffu, ss, o);
        const float res = myv / sqrtf(ss + 1e-7f);
        if (it == 2) out[(size_t)bidx * O_DIM + w * 32 + lane] = res;
        else outsm[w * 32 + lane] = res;
    }
}

extern "C" void kernel_launch(void* const* d_in, const int* in_sizes, int n_in,
                              void* d_out, int out_size) {
    const float* x = (const float*)d_in[0];
    const float* W = (const float*)d_in[1];
    float* out = (float*)d_out;

    split_x<<<32768, 256>>>(x);   // M*256/4/256
    split_w<<<512, 256>>>(W);
    zero_colsum<<<256, 512>>>();
    cudaFuncSetAttribute(caps_gemm, cudaFuncAttributeMaxDynamicSharedMemorySize, SMEM_DYN);
    dim3 grid(O_DIM / 128, M_DIM / 128);  // (4, 1024)
    caps_gemm<<<grid, 256, SMEM_DYN>>>();
    caps_routing<<<B_DIM, 512>>>(out);
}

// round 12
// speedup vs baseline: 3.3056x; 1.0065x over previous
#include <cuda_runtime.h>
#include <cuda_fp16.h>
#include <cstdint>

#define NC 16
#define DC 32
#define S_DIM 512
#define D_DIM 256
#define O_DIM 512
#define B_DIM 256
#define M_DIM (B_DIM * S_DIM)  // 131072

// u_hat TRANSPOSED, fp16: [b][o][s]
__device__ __half g_uhat[(size_t)B_DIM * O_DIM * S_DIM];
__device__ float g_colsum[(size_t)B_DIM * O_DIM];
// single fp16 conversions
__device__ __half g_xs[(size_t)M_DIM * 256];
__device__ __half g_ws[256 * 512];

// ---------------- PTX helpers ----------------
#define LDMX4(r, addr)                                                                   \
    asm volatile("ldmatrix.sync.aligned.m8n8.x4.shared.b16 {%0,%1,%2,%3}, [%4];"         \
                 : "=r"((r)[0]), "=r"((r)[1]), "=r"((r)[2]), "=r"((r)[3]) : "r"(addr))
#define LDMX4T(r, addr)                                                                  \
    asm volatile("ldmatrix.sync.aligned.m8n8.x4.trans.shared.b16 {%0,%1,%2,%3}, [%4];"   \
                 : "=r"((r)[0]), "=r"((r)[1]), "=r"((r)[2]), "=r"((r)[3]) : "r"(addr))
#define MMA_FP16(d, a, b0, b1)                                                           \
    asm volatile("mma.sync.aligned.m16n8k16.row.col.f32.f16.f16.f32 "                    \
                 "{%0,%1,%2,%3}, {%4,%5,%6,%7}, {%8,%9}, {%0,%1,%2,%3};"                 \
                 : "+f"((d)[0]), "+f"((d)[1]), "+f"((d)[2]), "+f"((d)[3])                \
                 : "r"((a)[0]), "r"((a)[1]), "r"((a)[2]), "r"((a)[3]), "r"(b0), "r"(b1))
#define CP16(dst, src)                                                                   \
    asm volatile("cp.async.cg.shared.global [%0], [%1], 16;" :: "r"(dst), "l"(src))
#define CPCOMMIT() asm volatile("cp.async.commit_group;")
#define CPWAIT(n)  asm volatile("cp.async.wait_group %0;" :: "n"(n))

__device__ __forceinline__ uint32_t smem_u32(const void* p) {
    uint32_t a;
    asm("{ .reg .u64 t; cvta.to.shared.u64 t, %1; cvt.u32.u64 %0, t; }" : "=r"(a) : "l"(p));
    return a;
}

// ---------------- convert precompute ----------------
__global__ __launch_bounds__(256) void split_x(const float* __restrict__ x) {
    const size_t j = (size_t)blockIdx.x * 256 + threadIdx.x;  // one float4 each
    const float4 f = *(const float4*)&x[j * 4];
    __half2 H0 = __floats2half2_rn(f.x, f.y);
    __half2 H1 = __floats2half2_rn(f.z, f.w);
    *(uint2*)&g_xs[j * 4] = make_uint2(*(uint32_t*)&H0, *(uint32_t*)&H1);
}

__global__ __launch_bounds__(256) void split_w(const float* __restrict__ W) {
    const int i = blockIdx.x * 256 + threadIdx.x;
    g_ws[i] = __float2half(W[i]);
    g_colsum[i] = 0.f;   // same element count (131072) — fused zeroing
}

// ---------------- GEMM: tile 128x128, BK=32, 256 threads, warp tile 32x64 ----------------
#define ASTR 40
#define BSTR 136
#define OFF_B  10240   // 128*40*2
#define STAGE  18944   // + 32*136*2 = 8704
#define SMEM_DYN (2 * STAGE)  // 37888; >= 64*132*4 = 33792 transpose buffer

__global__ __launch_bounds__(256, 2) void caps_gemm() {
    extern __shared__ char sm[];
    const uint32_t smb = smem_u32(sm);
    const int tid = threadIdx.x;
    const int wid = tid >> 5, lane = tid & 31;
    const int wm = wid >> 1, wn = wid & 1;   // 4m x 2n warps, warp tile 32x64
    const int m0 = blockIdx.y * 128;
    const int n0 = blockIdx.x * 128;

    const int arow = tid >> 1, ahalf = tid & 1;
    const int brow = tid >> 4, bg = tid & 15;
    const uint64_t srcA = __cvta_generic_to_global(&g_xs[(size_t)(m0 + arow) * 256 + ahalf * 16]);
    const uint64_t srcB = __cvta_generic_to_global(&g_ws[(size_t)brow * 512 + n0 + bg * 8]);
    const uint32_t dstA = smb + (uint32_t)(arow * ASTR + ahalf * 16) * 2;
    const uint32_t dstB = smb + OFF_B + (uint32_t)(brow * BSTR + bg * 8) * 2;

    const int mat = lane >> 3, r = lane & 7;
    uint32_t a_off[2], b_off[4];
#pragma unroll
    for (int fm = 0; fm < 2; fm++)
        a_off[fm] = (uint32_t)(((wm * 32 + fm * 16 + (mat & 1) * 8 + r) * ASTR + (mat >> 1) * 8) * 2);
#pragma unroll
    for (int nb = 0; nb < 4; nb++)
        b_off[nb] = (uint32_t)((((mat & 1) * 8 + r) * BSTR + (mat >> 1) * 8 + wn * 64 + nb * 16) * 2);

    float acc[2][8][4];
#pragma unroll
    for (int i = 0; i < 2; i++)
#pragma unroll
        for (int j = 0; j < 8; j++)
#pragma unroll
            for (int k = 0; k < 4; k++) acc[i][j][k] = 0.f;

#define ISSUE(kc) do {                                                     \
        const uint32_t bb = ((kc) & 1) * STAGE;                            \
        const uint64_t ka = (uint64_t)(kc) * 64;                           \
        CP16(dstA + bb, srcA + ka); CP16(dstA + bb + 16, srcA + ka + 16);  \
        const uint64_t kb = (uint64_t)(kc) * 32768;                        \
        CP16(dstB + bb, srcB + kb);                                        \
        CP16(dstB + bb + 16 * BSTR * 2, srcB + kb + 16 * 512 * 2);         \
        CPCOMMIT();                                                        \
    } while (0)

    ISSUE(0);
    for (int kc = 0; kc < 8; kc++) {
        if (kc < 7) { ISSUE(kc + 1); CPWAIT(1); } else { CPWAIT(0); }
        __syncthreads();
        const uint32_t sb = smb + (kc & 1) * STAGE;
#pragma unroll
        for (int ks = 0; ks < 2; ks++) {
            uint32_t Af[2][4], Bf[4][4];
#pragma unroll
            for (int fm = 0; fm < 2; fm++)
                LDMX4(Af[fm], sb + a_off[fm] + ks * 32);
#pragma unroll
            for (int nb = 0; nb < 4; nb++)
                LDMX4T(Bf[nb], sb + OFF_B + b_off[nb] + ks * 16 * BSTR * 2);
#pragma unroll
            for (int nb = 0; nb < 4; nb++)
#pragma unroll
                for (int fm = 0; fm < 2; fm++)
#pragma unroll
                    for (int h = 0; h < 2; h++)
                        MMA_FP16(acc[fm][nb * 2 + h], Af[fm], Bf[nb][h * 2], Bf[nb][h * 2 + 1]);
        }
        __syncthreads();
    }

    // ---- epilogue: two o-half passes; transpose + fp16 write + colsums ----
    float* smt = (float*)sm;  // [64 o][132 s-pad]
    const int b = m0 >> 9;
    const int sbase = m0 & 511;
    const int ol = tid >> 2, seg = tid & 3;
#pragma unroll
    for (int p = 0; p < 2; p++) {
        __syncthreads();
        if (wn == p) {
#pragma unroll
            for (int fm = 0; fm < 2; fm++) {
                const int sl = wm * 32 + fm * 16 + (lane >> 2);
#pragma unroll
                for (int fn = 0; fn < 8; fn++) {
                    const int oc = fn * 8 + (lane & 3) * 2;
                    smt[oc * 132 + sl] = acc[fm][fn][0];
                    smt[(oc + 1) * 132 + sl] = acc[fm][fn][1];
                    smt[oc * 132 + sl + 8] = acc[fm][fn][2];
                    smt[(oc + 1) * 132 + sl + 8] = acc[fm][fn][3];
                }
            }
        }
        __syncthreads();
        __half* dst = &g_uhat[((size_t)b * 512 + n0 + p * 64 + ol) * 512 + sbase + seg * 32];
        const float* srcT = &smt[ol * 132 + seg * 32];
        float csum = 0.f;
#pragma unroll
        for (int j = 0; j < 4; j++) {
            const float4 v0 = *(const float4*)&srcT[j * 8];
            const float4 v1 = *(const float4*)&srcT[j * 8 + 4];
            csum += (v0.x + v0.y) + (v0.z + v0.w) + (v1.x + v1.y) + (v1.z + v1.w);
            __half2 p0 = __floats2half2_rn(v0.x, v0.y);
            __half2 p1 = __floats2half2_rn(v0.z, v0.w);
            __half2 p2 = __floats2half2_rn(v1.x, v1.y);
            __half2 p3 = __floats2half2_rn(v1.z, v1.w);
            uint4 o;
            o.x = *(uint32_t*)&p0; o.y = *(uint32_t*)&p1;
            o.z = *(uint32_t*)&p2; o.w = *(uint32_t*)&p3;
            *(uint4*)&dst[j * 8] = o;
        }
        atomicAdd(&g_colsum[(size_t)b * 512 + n0 + p * 64 + ol], csum);
    }
}

// ---------------- Routing: passes 1,2; low-reg (val reloaded, L1 hits), 2 CTAs/SM ----------------
__global__ __launch_bounds__(512, 2) void caps_routing(float* __restrict__ out) {
    __shared__ float outsm[O_DIM];
    __shared__ float bsm[NC][33];
    __shared__ float csm[32][17];
    const int bidx = blockIdx.x;
    const int lane = threadIdx.x & 31;
    const int w = threadIdx.x >> 5;
    const __half* __restrict__ u =
        g_uhat + (size_t)bidx * O_DIM * S_DIM + (size_t)w * 32 * S_DIM + lane;

    {
        const float myv = g_colsum[(size_t)bidx * 512 + threadIdx.x] * (1.f / 16.f);
        float ss = myv * myv;
#pragma unroll
        for (int o = 16; o > 0; o >>= 1) ss += __shfl_xor_sync(0xffffffffu, ss, o);
        outsm[threadIdx.x] = myv / sqrtf(ss + 1e-7f);
    }

    float acc[32];
    for (int it = 1; it < 3; it++) {
        __syncthreads();
#pragma unroll
        for (int r2 = 0; r2 < 32; r2++) acc[r2] = 0.f;

        for (int chunk = 0; chunk < 16; chunk++) {
            const __half* up = u + chunk * 32;

            // phase A: logits (values streamed, not kept live)
            float bl = 0.f;
#pragma unroll
            for (int r2 = 0; r2 < 32; r2++)
                bl += outsm[w * 32 + r2] * __half2float(up[(size_t)r2 * S_DIM]);
            bsm[w][lane] = bl;
            __syncthreads();

            {
                const int sp = lane >> 4, n = lane & 15;
                const float bv = bsm[n][2 * w + sp];
                float mx = bv;
#pragma unroll
                for (int o = 8; o > 0; o >>= 1) mx = fmaxf(mx, __shfl_xor_sync(0xffffffffu, mx, o));
                const float e = __expf(bv - mx);
                float den = e;
#pragma unroll
                for (int o = 8; o > 0; o >>= 1) den += __shfl_xor_sync(0xffffffffu, den, o);
                csm[2 * w + sp][n] = e / den;
            }
            __syncthreads();

            // phase B: accumulate (reload u — L1 hits)
            const float cw = csm[lane][w];
#pragma unroll
            for (int r2 = 0; r2 < 32; r2++)
                acc[r2] += cw * __half2float(up[(size_t)r2 * S_DIM]);
        }

        float myv = 0.f;
#pragma unroll
        for (int r2 = 0; r2 < 32; r2++) {
            float t = acc[r2];
#pragma unroll
            for (int o = 16; o > 0; o >>= 1) t += __shfl_xor_sync(0xffffffffu, t, o);
            if (lane == r2) myv = t;
        }
        float ss = myv * myv;
#pragma unroll
        for (int o = 16; o > 0; o >>= 1) ss += __shfl_xor_sync(0xffffffffu, ss, o);
        const float res = myv / sqrtf(ss + 1e-7f);
        if (it == 2) out[(size_t)bidx * O_DIM + w * 32 + lane] = res;
        else outsm[w * 32 + lane] = res;
    }
}

extern "C" void kernel_launch(void* const* d_in, const int* in_sizes, int n_in,
                              void* d_out, int out_size) {
    const float* x = (const float*)d_in[0];
    const float* W = (const float*)d_in[1];
    float* out = (float*)d_out;

    split_x<<<32768, 256>>>(x);
    split_w<<<512, 256>>>(W);   // also zeroes g_colsum
    cudaFuncSetAttribute(caps_gemm, cudaFuncAttributeMaxDynamicSharedMemorySize, SMEM_DYN);
    dim3 grid(O_DIM / 128, M_DIM / 128);  // (4, 1024)
    caps_gemm<<<grid, 256, SMEM_DYN>>>();
    caps_routing<<<B_DIM, 512>>>(out);
}

// round 13
// speedup vs baseline: 3.6015x; 1.0895x over previous
#include <cuda_runtime.h>
#include <cuda_fp16.h>
#include <cstdint>

#define NC 16
#define DC 32
#define S_DIM 512
#define D_DIM 256
#define O_DIM 512
#define B_DIM 256
#define M_DIM (B_DIM * S_DIM)  // 131072

// u_hat TRANSPOSED, fp16: [b][o][s]
__device__ __half g_uhat[(size_t)B_DIM * O_DIM * S_DIM];
__device__ float g_colsum[(size_t)B_DIM * O_DIM];
// single fp16 conversions
__device__ __half g_xs[(size_t)M_DIM * 256];
__device__ __half g_ws[256 * 512];

// ---------------- PTX helpers ----------------
#define LDMX4(r, addr)                                                                   \
    asm volatile("ldmatrix.sync.aligned.m8n8.x4.shared.b16 {%0,%1,%2,%3}, [%4];"         \
                 : "=r"((r)[0]), "=r"((r)[1]), "=r"((r)[2]), "=r"((r)[3]) : "r"(addr))
#define LDMX4T(r, addr)                                                                  \
    asm volatile("ldmatrix.sync.aligned.m8n8.x4.trans.shared.b16 {%0,%1,%2,%3}, [%4];"   \
                 : "=r"((r)[0]), "=r"((r)[1]), "=r"((r)[2]), "=r"((r)[3]) : "r"(addr))
#define MMA_FP16(d, a, b0, b1)                                                           \
    asm volatile("mma.sync.aligned.m16n8k16.row.col.f32.f16.f16.f32 "                    \
                 "{%0,%1,%2,%3}, {%4,%5,%6,%7}, {%8,%9}, {%0,%1,%2,%3};"                 \
                 : "+f"((d)[0]), "+f"((d)[1]), "+f"((d)[2]), "+f"((d)[3])                \
                 : "r"((a)[0]), "r"((a)[1]), "r"((a)[2]), "r"((a)[3]), "r"(b0), "r"(b1))
#define CP16(dst, src)                                                                   \
    asm volatile("cp.async.cg.shared.global [%0], [%1], 16;" :: "r"(dst), "l"(src))
#define CPCOMMIT() asm volatile("cp.async.commit_group;")
#define CPWAIT(n)  asm volatile("cp.async.wait_group %0;" :: "n"(n))

__device__ __forceinline__ uint32_t smem_u32(const void* p) {
    uint32_t a;
    asm("{ .reg .u64 t; cvta.to.shared.u64 t, %1; cvt.u32.u64 %0, t; }" : "=r"(a) : "l"(p));
    return a;
}

// ---------------- convert precompute ----------------
__global__ __launch_bounds__(256) void split_x(const float* __restrict__ x) {
    const size_t j = (size_t)blockIdx.x * 256 + threadIdx.x;
    const float4 f = *(const float4*)&x[j * 4];
    __half2 H0 = __floats2half2_rn(f.x, f.y);
    __half2 H1 = __floats2half2_rn(f.z, f.w);
    *(uint2*)&g_xs[j * 4] = make_uint2(*(uint32_t*)&H0, *(uint32_t*)&H1);
}

__global__ __launch_bounds__(256) void split_w(const float* __restrict__ W) {
    const int i = blockIdx.x * 256 + threadIdx.x;
    g_ws[i] = __float2half(W[i]);
    g_colsum[i] = 0.f;
}

// ---------------- GEMM: tile 128x128, BK=32, 256 threads, warp tile 32x64 ----------------
#define ASTR 40
#define BSTR 136
#define OFF_B  10240
#define STAGE  18944
#define SMEM_DYN (2 * STAGE)

__global__ __launch_bounds__(256, 2) void caps_gemm() {
    extern __shared__ char sm[];
    const uint32_t smb = smem_u32(sm);
    const int tid = threadIdx.x;
    const int wid = tid >> 5, lane = tid & 31;
    const int wm = wid >> 1, wn = wid & 1;
    const int m0 = blockIdx.y * 128;
    const int n0 = blockIdx.x * 128;

    const int arow = tid >> 1, ahalf = tid & 1;
    const int brow = tid >> 4, bg = tid & 15;
    const uint64_t srcA = __cvta_generic_to_global(&g_xs[(size_t)(m0 + arow) * 256 + ahalf * 16]);
    const uint64_t srcB = __cvta_generic_to_global(&g_ws[(size_t)brow * 512 + n0 + bg * 8]);
    const uint32_t dstA = smb + (uint32_t)(arow * ASTR + ahalf * 16) * 2;
    const uint32_t dstB = smb + OFF_B + (uint32_t)(brow * BSTR + bg * 8) * 2;

    const int mat = lane >> 3, r = lane & 7;
    uint32_t a_off[2], b_off[4];
#pragma unroll
    for (int fm = 0; fm < 2; fm++)
        a_off[fm] = (uint32_t)(((wm * 32 + fm * 16 + (mat & 1) * 8 + r) * ASTR + (mat >> 1) * 8) * 2);
#pragma unroll
    for (int nb = 0; nb < 4; nb++)
        b_off[nb] = (uint32_t)((((mat & 1) * 8 + r) * BSTR + (mat >> 1) * 8 + wn * 64 + nb * 16) * 2);

    float acc[2][8][4];
#pragma unroll
    for (int i = 0; i < 2; i++)
#pragma unroll
        for (int j = 0; j < 8; j++)
#pragma unroll
            for (int k = 0; k < 4; k++) acc[i][j][k] = 0.f;

#define ISSUE(kc) do {                                                     \
        const uint32_t bb = ((kc) & 1) * STAGE;                            \
        const uint64_t ka = (uint64_t)(kc) * 64;                           \
        CP16(dstA + bb, srcA + ka); CP16(dstA + bb + 16, srcA + ka + 16);  \
        const uint64_t kb = (uint64_t)(kc) * 32768;                        \
        CP16(dstB + bb, srcB + kb);                                        \
        CP16(dstB + bb + 16 * BSTR * 2, srcB + kb + 16 * 512 * 2);         \
        CPCOMMIT();                                                        \
    } while (0)

    ISSUE(0);
    for (int kc = 0; kc < 8; kc++) {
        if (kc < 7) { ISSUE(kc + 1); CPWAIT(1); } else { CPWAIT(0); }
        __syncthreads();
        const uint32_t sb = smb + (kc & 1) * STAGE;
#pragma unroll
        for (int ks = 0; ks < 2; ks++) {
            uint32_t Af[2][4], Bf[4][4];
#pragma unroll
            for (int fm = 0; fm < 2; fm++)
                LDMX4(Af[fm], sb + a_off[fm] + ks * 32);
#pragma unroll
            for (int nb = 0; nb < 4; nb++)
                LDMX4T(Bf[nb], sb + OFF_B + b_off[nb] + ks * 16 * BSTR * 2);
#pragma unroll
            for (int nb = 0; nb < 4; nb++)
#pragma unroll
                for (int fm = 0; fm < 2; fm++)
#pragma unroll
                    for (int h = 0; h < 2; h++)
                        MMA_FP16(acc[fm][nb * 2 + h], Af[fm], Bf[nb][h * 2], Bf[nb][h * 2 + 1]);
        }
        __syncthreads();
    }

    // ---- epilogue: two o-half passes; transpose + fp16 write + colsums ----
    float* smt = (float*)sm;
    const int b = m0 >> 9;
    const int sbase = m0 & 511;
    const int ol = tid >> 2, seg = tid & 3;
#pragma unroll
    for (int p = 0; p < 2; p++) {
        __syncthreads();
        if (wn == p) {
#pragma unroll
            for (int fm = 0; fm < 2; fm++) {
                const int sl = wm * 32 + fm * 16 + (lane >> 2);
#pragma unroll
                for (int fn = 0; fn < 8; fn++) {
                    const int oc = fn * 8 + (lane & 3) * 2;
                    smt[oc * 132 + sl] = acc[fm][fn][0];
                    smt[(oc + 1) * 132 + sl] = acc[fm][fn][1];
                    smt[oc * 132 + sl + 8] = acc[fm][fn][2];
                    smt[(oc + 1) * 132 + sl + 8] = acc[fm][fn][3];
                }
            }
        }
        __syncthreads();
        __half* dst = &g_uhat[((size_t)b * 512 + n0 + p * 64 + ol) * 512 + sbase + seg * 32];
        const float* srcT = &smt[ol * 132 + seg * 32];
        float csum = 0.f;
#pragma unroll
        for (int j = 0; j < 4; j++) {
            const float4 v0 = *(const float4*)&srcT[j * 8];
            const float4 v1 = *(const float4*)&srcT[j * 8 + 4];
            csum += (v0.x + v0.y) + (v0.z + v0.w) + (v1.x + v1.y) + (v1.z + v1.w);
            __half2 p0 = __floats2half2_rn(v0.x, v0.y);
            __half2 p1 = __floats2half2_rn(v0.z, v0.w);
            __half2 p2 = __floats2half2_rn(v1.x, v1.y);
            __half2 p3 = __floats2half2_rn(v1.z, v1.w);
            uint4 o;
            o.x = *(uint32_t*)&p0; o.y = *(uint32_t*)&p1;
            o.z = *(uint32_t*)&p2; o.w = *(uint32_t*)&p3;
            *(uint4*)&dst[j * 8] = o;
        }
        atomicAdd(&g_colsum[(size_t)b * 512 + n0 + p * 64 + ol], csum);
    }
}

// ---------------- Routing: half2 loads, 64-s chunks, 2 CTAs/SM ----------------
__global__ __launch_bounds__(512, 2) void caps_routing(float* __restrict__ out) {
    __shared__ float outsm[O_DIM];
    __shared__ float bsm[NC][66];   // [n][s_local], float2-aligned rows
    __shared__ float csm[64][17];   // [s_local][n]
    const int bidx = blockIdx.x;
    const int lane = threadIdx.x & 31;
    const int w = threadIdx.x >> 5;  // capsule n
    const __half* __restrict__ u =
        g_uhat + (size_t)bidx * O_DIM * S_DIM + (size_t)w * 32 * S_DIM;

    // pass 0 result from fused column sums
    {
        const float myv = g_colsum[(size_t)bidx * 512 + threadIdx.x] * (1.f / 16.f);
        float ss = myv * myv;
#pragma unroll
        for (int o = 16; o > 0; o >>= 1) ss += __shfl_xor_sync(0xffffffffu, ss, o);
        outsm[threadIdx.x] = myv / sqrtf(ss + 1e-7f);
    }

    float acc[32];
    for (int it = 1; it < 3; it++) {
        __syncthreads();
#pragma unroll
        for (int r2 = 0; r2 < 32; r2++) acc[r2] = 0.f;

        for (int chunk = 0; chunk < 8; chunk++) {
            // lane owns s pair (chunk*64 + 2*lane, +1)
            const __half2* up2 = (const __half2*)(u + chunk * 64) + lane;

            // phase A: logits, 4 independent chains
            float bl0a = 0.f, bl0b = 0.f, bl1a = 0.f, bl1b = 0.f;
#pragma unroll
            for (int r2 = 0; r2 < 32; r2 += 2) {
                const float2 v0 = __half22float2(up2[(size_t)r2 * 256]);
                const float2 v1 = __half22float2(up2[(size_t)(r2 + 1) * 256]);
                const float o0 = outsm[w * 32 + r2];
                const float o1 = outsm[w * 32 + r2 + 1];
                bl0a += o0 * v0.x; bl1a += o0 * v0.y;
                bl0b += o1 * v1.x; bl1b += o1 * v1.y;
            }
            *(float2*)&bsm[w][2 * lane] = make_float2(bl0a + bl0b, bl1a + bl1b);
            __syncthreads();

            // softmax over n; thread (w, n=lane&15, q=lane>>4) handles s_local = 4w+2q+r
            {
                const int q = lane >> 4, n = lane & 15;
#pragma unroll
                for (int r = 0; r < 2; r++) {
                    const int sl = 4 * w + 2 * q + r;
                    const float bv = bsm[n][sl];
                    float mx = bv;
#pragma unroll
                    for (int o = 8; o > 0; o >>= 1)
                        mx = fmaxf(mx, __shfl_xor_sync(0xffffffffu, mx, o));
                    const float e = __expf(bv - mx);
                    float den = e;
#pragma unroll
                    for (int o = 8; o > 0; o >>= 1)
                        den += __shfl_xor_sync(0xffffffffu, den, o);
                    csm[sl][n] = e / den;
                }
            }
            __syncthreads();

            // phase B: accumulate (reload u — L1-hot, 4B loads)
            const float cw0 = csm[2 * lane][w];
            const float cw1 = csm[2 * lane + 1][w];
#pragma unroll
            for (int r2 = 0; r2 < 32; r2++) {
                const float2 v = __half22float2(up2[(size_t)r2 * 256]);
                acc[r2] += cw0 * v.x + cw1 * v.y;
            }
        }

        float myv = 0.f;
#pragma unroll
        for (int r2 = 0; r2 < 32; r2++) {
            float t = acc[r2];
#pragma unroll
            for (int o = 16; o > 0; o >>= 1) t += __shfl_xor_sync(0xffffffffu, t, o);
            if (lane == r2) myv = t;
        }
        float ss = myv * myv;
#pragma unroll
        for (int o = 16; o > 0; o >>= 1) ss += __shfl_xor_sync(0xffffffffu, ss, o);
        const float res = myv / sqrtf(ss + 1e-7f);
        if (it == 2) out[(size_t)bidx * O_DIM + w * 32 + lane] = res;
        else outsm[w * 32 + lane] = res;
    }
}

extern "C" void kernel_launch(void* const* d_in, const int* in_sizes, int n_in,
                              void* d_out, int out_size) {
    const float* x = (const float*)d_in[0];
    const float* W = (const float*)d_in[1];
    float* out = (float*)d_out;

    split_x<<<32768, 256>>>(x);
    split_w<<<512, 256>>>(W);   // also zeroes g_colsum
    cudaFuncSetAttribute(caps_gemm, cudaFuncAttributeMaxDynamicSharedMemorySize, SMEM_DYN);
    dim3 grid(O_DIM / 128, M_DIM / 128);  // (4, 1024)
    caps_gemm<<<grid, 256, SMEM_DYN>>>();
    caps_routing<<<B_DIM, 512>>>(out);
}